// round 4
// baseline (speedup 1.0000x reference)
#include <cuda_runtime.h>
#include <cstdint>

#define TT    8
#define LL    197
#define HH    12
#define DD    64
#define LK    196
#define NPAIR 112
#define CDIM  768
#define WSZ   729        // (2*14-1)^2
#define KPAD  224        // per-half k padded

// attn scratch, pre-split tf32 (hi,lo): [half][q 196][pair 112][KPAD]
__device__ float2 g_attn2[2u * LK * NPAIR * KPAD];
// pre-split w1/w2: [WSZ][768]
__device__ float2 g_w1s[WSZ * CDIM];
__device__ float2 g_w2s[WSZ * CDIM];
// zero source for cp.async of invalid rows (>=256B)
__device__ ulonglong2 g_zero4[16];  // zero-initialized

__device__ __forceinline__ void cp16(uint32_t dst, const void* src) {
    asm volatile("cp.async.cg.shared.global [%0], [%1], 16;" :: "r"(dst), "l"(src));
}
__device__ __forceinline__ void split_tf32(float x, uint32_t& hi, uint32_t& lo) {
    uint32_t h;
    asm("cvt.rna.tf32.f32 %0, %1;" : "=r"(h) : "f"(x));
    float lf = x - __uint_as_float(h);
    uint32_t l;
    asm("cvt.rna.tf32.f32 %0, %1;" : "=r"(l) : "f"(lf));
    hi = h; lo = l;
}
__device__ __forceinline__ void mma8(float* c,
    uint32_t a0, uint32_t a1, uint32_t a2, uint32_t a3, uint32_t b0, uint32_t b1)
{
    asm volatile("mma.sync.aligned.m16n8k8.row.col.f32.tf32.tf32.f32 "
        "{%0,%1,%2,%3},{%4,%5,%6,%7},{%8,%9},{%0,%1,%2,%3};"
        : "+f"(c[0]), "+f"(c[1]), "+f"(c[2]), "+f"(c[3])
        : "r"(a0), "r"(a1), "r"(a2), "r"(a3), "r"(b0), "r"(b1));
}
#define U(x) __float_as_uint(x)

// ===========================================================================
// Kernel 1: tf32 scores + softmax + head-mean, d-chunked, shared K-split
// grid (2 qtiles, 112 pairs, 2 halves) x 448 threads (14 warps)
// smem (floats): QRAW 2x112x36 | KRAW 196x32 | KSPLIT 196x36 f2 | RED 224
// ===========================================================================
#define K1_THREADS 448
#define QROWS 112
#define QP    36
#define QBUF  (QROWS * QP)            // 4032
#define QS_OFF   0
#define KRAW_OFF (2 * QBUF)           // 8064
#define KSPL_OFF (KRAW_OFF + LK * 32) // 8064+6272 = 14336 (float offset; f2 base)
#define RED_OFF  (KSPL_OFF + LK * 36 * 2)  // 14336 + 14112 = 28448
#define SMEM1_FLOATS (RED_OFF + 224)       // 28672
#define SMEM1_BYTES (SMEM1_FLOATS * 4)     // 114688

__device__ __forceinline__ void k1_load_raw(
    const float* __restrict__ q, const float* __restrict__ k,
    size_t qbase, size_t kbase, int q0, int tid, uint32_t smem_u32, int i)
{
    const int colbase = (i >> 1) * 64 + (i & 1) * 32;
    const int buf = i & 1;
    // Q: 112 rows x 8 float4
#pragma unroll
    for (int it = 0; it < 2; it++) {
        int i2 = tid + it * K1_THREADS;
        int row = i2 >> 3, c4 = i2 & 7;
        int qg = q0 + row; if (qg > 195) qg = 195;
        const float* src = q + qbase + (size_t)qg * (HH * DD) + colbase + c4 * 4;
        cp16(smem_u32 + (uint32_t)(QS_OFF + buf * QBUF + row * QP + c4 * 4) * 4, src);
    }
    // K: 196 rows x 8 float4
#pragma unroll
    for (int it = 0; it < 4; it++) {
        int i2 = tid + it * K1_THREADS;
        if (i2 < LK * 8) {
            int row = i2 >> 3, c4 = i2 & 7;
            const float* src = k + kbase + (size_t)row * (HH * DD) + colbase + c4 * 4;
            cp16(smem_u32 + (uint32_t)(KRAW_OFF + row * 32 + c4 * 4) * 4, src);
        }
    }
    asm volatile("cp.async.commit_group;");
}

__global__ void __launch_bounds__(K1_THREADS) attn_tc_kernel(
    const float* __restrict__ q, const float* __restrict__ k)
{
    extern __shared__ float sm[];
    float2* ksp = (float2*)(sm + KSPL_OFF);
    const int tid = threadIdx.x;
    const int lane = tid & 31;
    const int wid = tid >> 5;
    const int stripe = wid >> 1;       // 0..6
    const int nhalf = wid & 1;
    const int qt = blockIdx.x;
    const int p = blockIdx.y;
    const int hf = blockIdx.z;
    const int n = p / 7, tp = p % 7;
    const int tq = (hf == 0) ? tp + 1 : tp;
    const int tk = (hf == 0) ? tp : tp + 1;
    const size_t qbase = ((size_t)(n * TT + tq) * LL + 1) * (HH * DD);
    const size_t kbase = ((size_t)(n * TT + tk) * LL + 1) * (HH * DD);
    const int q0 = qt * QROWS;

    uint32_t smem_u32;
    asm("{ .reg .u64 t; cvta.to.shared.u64 t, %1; cvt.u32.u64 %0, t; }"
        : "=r"(smem_u32) : "l"(sm));

    const int nt0 = nhalf ? 13 : 0;
    const int cnt = nhalf ? 12 : 13;
    const int rA = stripe * 16 + (lane >> 2);
    const int rB = rA + 8;

    float macc[13][4];
#pragma unroll
    for (int t = 0; t < 13; t++)
#pragma unroll
        for (int j = 0; j < 4; j++) macc[t][j] = 0.f;

    // prologue: chunk 0 -> raw, convert, prefetch chunk 1
    k1_load_raw(q, k, qbase, kbase, q0, tid, smem_u32, 0);
    asm volatile("cp.async.wait_group 0;");
    __syncthreads();
#pragma unroll
    for (int j = 0; j < 14; j++) {
        int e = tid + j * K1_THREADS;                 // 6272 = 448*14
        float x = sm[KRAW_OFF + e];
        uint32_t hi, lo; split_tf32(x, hi, lo);
        ksp[(e >> 5) * QP + (e & 31)] =
            make_float2(__uint_as_float(hi), __uint_as_float(lo));
    }
    __syncthreads();
    k1_load_raw(q, k, qbase, kbase, q0, tid, smem_u32, 1);

    float c[13][4];

    for (int i = 0; i < 24; i++) {
        const int dc = i & 1;
        const float* qsr = sm + QS_OFF + (i & 1) * QBUF;

        if (dc == 0) {
#pragma unroll
            for (int t = 0; t < 13; t++)
#pragma unroll
                for (int j = 0; j < 4; j++) c[t][j] = 0.f;
        }

#pragma unroll
        for (int kc = 0; kc < 4; kc++) {
            const int dcol = kc * 8 + (lane & 3);
            float a0f = qsr[rA * QP + dcol];
            float a1f = qsr[rB * QP + dcol];
            float a2f = qsr[rA * QP + dcol + 4];
            float a3f = qsr[rB * QP + dcol + 4];
            uint32_t ah0, al0, ah1, al1, ah2, al2, ah3, al3;
            split_tf32(a0f, ah0, al0);
            split_tf32(a1f, ah1, al1);
            split_tf32(a2f, ah2, al2);
            split_tf32(a3f, ah3, al3);
#pragma unroll
            for (int t = 0; t < 13; t++) {
                if (t < cnt) {
                    int brow = (nt0 + t) * 8 + (lane >> 2);
                    if (brow > 195) brow = 195;
                    float2 b0 = ksp[brow * QP + dcol];
                    float2 b1 = ksp[brow * QP + dcol + 4];
                    mma8(c[t], ah0, ah1, ah2, ah3, U(b0.x), U(b1.x));
                    mma8(c[t], al0, al1, al2, al3, U(b0.x), U(b1.x));
                    mma8(c[t], ah0, ah1, ah2, ah3, U(b0.y), U(b1.y));
                }
            }
        }

        if (dc == 1) {
            // mask invalid n (cols 196..199: nhalf, local t==11, (lane&3)>=2)
            if (nhalf && (lane & 3) >= 2) {
                c[11][0] = -1e30f; c[11][1] = -1e30f;
                c[11][2] = -1e30f; c[11][3] = -1e30f;
            }
            float mA = -1e30f, mB = -1e30f;
#pragma unroll
            for (int t = 0; t < 13; t++) {
                if (t < cnt) {
                    mA = fmaxf(mA, fmaxf(c[t][0], c[t][1]));
                    mB = fmaxf(mB, fmaxf(c[t][2], c[t][3]));
                }
            }
#pragma unroll
            for (int o = 1; o <= 2; o <<= 1) {
                mA = fmaxf(mA, __shfl_xor_sync(0xffffffffu, mA, o));
                mB = fmaxf(mB, __shfl_xor_sync(0xffffffffu, mB, o));
            }
            if ((lane & 3) == 0) {
                sm[RED_OFF + rA * 2 + nhalf] = mA;
                sm[RED_OFF + rB * 2 + nhalf] = mB;
            }
            __syncthreads();
            mA = fmaxf(mA, sm[RED_OFF + rA * 2 + (1 - nhalf)]);
            mB = fmaxf(mB, sm[RED_OFF + rB * 2 + (1 - nhalf)]);

            float sA = 0.f, sB = 0.f;
#pragma unroll
            for (int t = 0; t < 13; t++) {
                if (t < cnt) {
                    c[t][0] = __expf((c[t][0] - mA) * 0.125f);
                    c[t][1] = __expf((c[t][1] - mA) * 0.125f);
                    c[t][2] = __expf((c[t][2] - mB) * 0.125f);
                    c[t][3] = __expf((c[t][3] - mB) * 0.125f);
                    sA += c[t][0] + c[t][1];
                    sB += c[t][2] + c[t][3];
                }
            }
#pragma unroll
            for (int o = 1; o <= 2; o <<= 1) {
                sA += __shfl_xor_sync(0xffffffffu, sA, o);
                sB += __shfl_xor_sync(0xffffffffu, sB, o);
            }
            __syncthreads();   // all max-reads done before RED reuse
            if ((lane & 3) == 0) {
                sm[RED_OFF + rA * 2 + nhalf] = sA;
                sm[RED_OFF + rB * 2 + nhalf] = sB;
            }
            __syncthreads();
            sA += sm[RED_OFF + rA * 2 + (1 - nhalf)];
            sB += sm[RED_OFF + rB * 2 + (1 - nhalf)];
            const float iA = 1.0f / (12.0f * sA);
            const float iB = 1.0f / (12.0f * sB);
#pragma unroll
            for (int t = 0; t < 13; t++) {
                if (t < cnt) {
                    macc[t][0] += c[t][0] * iA;
                    macc[t][1] += c[t][1] * iA;
                    macc[t][2] += c[t][2] * iB;
                    macc[t][3] += c[t][3] * iB;
                }
            }
        }

        if (i < 23) {
            asm volatile("cp.async.wait_group 0;");
            __syncthreads();
#pragma unroll
            for (int j = 0; j < 14; j++) {
                int e = tid + j * K1_THREADS;
                float x = sm[KRAW_OFF + e];
                uint32_t hi, lo; split_tf32(x, hi, lo);
                ksp[(e >> 5) * QP + (e & 31)] =
                    make_float2(__uint_as_float(hi), __uint_as_float(lo));
            }
            __syncthreads();
            if (i < 22) k1_load_raw(q, k, qbase, kbase, q0, tid, smem_u32, i + 2);
        }
    }

    // epilogue: split macc -> stage (28 rows x 224 f2) -> coalesced f4 stores
    float2* stg = (float2*)sm;
    for (int pass = 0; pass < 4; pass++) {
        __syncthreads();
#pragma unroll
        for (int j = 0; j < 14; j++) stg[tid + j * K1_THREADS] = make_float2(0.f, 0.f);
        __syncthreads();
        const int rlo = pass * 28, rhi = rlo + 28;
#pragma unroll
        for (int t = 0; t < 13; t++) {
            if (t < cnt) {
                const int col = (nt0 + t) * 8 + 2 * (lane & 3);
                if (col < 195) {
                    if (rA >= rlo && rA < rhi) {
                        uint32_t h0, l0, h1, l1;
                        split_tf32(macc[t][0], h0, l0);
                        split_tf32(macc[t][1], h1, l1);
                        stg[(rA - rlo) * KPAD + col] =
                            make_float2(__uint_as_float(h0), __uint_as_float(l0));
                        stg[(rA - rlo) * KPAD + col + 1] =
                            make_float2(__uint_as_float(h1), __uint_as_float(l1));
                    }
                    if (rB >= rlo && rB < rhi) {
                        uint32_t h0, l0, h1, l1;
                        split_tf32(macc[t][2], h0, l0);
                        split_tf32(macc[t][3], h1, l1);
                        stg[(rB - rlo) * KPAD + col] =
                            make_float2(__uint_as_float(h0), __uint_as_float(l0));
                        stg[(rB - rlo) * KPAD + col + 1] =
                            make_float2(__uint_as_float(h1), __uint_as_float(l1));
                    }
                }
            }
        }
        __syncthreads();
#pragma unroll
        for (int j = 0; j < 7; j++) {
            int i2 = tid + j * K1_THREADS;       // 3136 float4 (= 28*224 f2)
            int row = i2 / 112, cf4 = i2 % 112;
            int qg = q0 + pass * 28 + row;
            if (qg < LK) {
                float4 v = *((const float4*)stg + i2);
                *((float4*)(g_attn2 + ((size_t)(hf * LK + qg) * NPAIR + p) * KPAD) + cf4) = v;
            }
        }
    }
}

// ===========================================================================
// Kernel 2: out = A(attn,split) @ W(gathered,split), tf32 MMA
// grid (12 c-tiles of 64, 196 q) x 256 threads (8 warps: 4 mpair x 2 nhalf)
// smem f2: A 2x(128x36) | W 2x(32x68) | idx 224 ints
// ===========================================================================
#define K2_THREADS 256
#define AP 36
#define WP 68
#define ABUF (128 * AP)     // 4608 f2
#define WBUF (32 * WP)      // 2176 f2
#define A_OFF 0
#define W_OFF (2 * ABUF)                    // 9216 f2
#define IDX_OFF ((2 * ABUF + 2 * WBUF) * 8) // byte offset 108544
#define SMEM2_BYTES (IDX_OFF + KPAD * 4)    // 109440

__device__ __forceinline__ void k2_load(
    int q, int c0, int tid, uint32_t smem_u32, const int* idxrow, int i)
{
    const int half = i / 7;
    const int kb = (i % 7) * 32;
    const int buf = i & 1;
    // A: 128 rows x 16 cp16 (32 f2 each)
#pragma unroll
    for (int it = 0; it < 8; it++) {
        int i2 = tid + it * K2_THREADS;
        int mrow = i2 >> 4, seg = i2 & 15;
        int nn = mrow >> 3, tt = mrow & 7;
        const float2* src;
        if (half == 0) {
            src = (tt >= 1) ? g_attn2 + ((size_t)(q) * NPAIR + nn * 7 + tt - 1) * KPAD + kb
                            : (const float2*)g_zero4;
        } else {
            src = (tt <= 6) ? g_attn2 + ((size_t)(LK + q) * NPAIR + nn * 7 + tt) * KPAD + kb
                            : (const float2*)g_zero4;
        }
        cp16(smem_u32 + (uint32_t)(A_OFF + buf * ABUF + mrow * AP) * 8 + seg * 16,
             src + seg * 2);
    }
    // W: 32 rows x 32 cp16 (64 f2 each)
    const float2* wbase = half ? g_w2s : g_w1s;
#pragma unroll
    for (int it = 0; it < 4; it++) {
        int i2 = tid + it * K2_THREADS;
        int kr = i2 >> 5, seg = i2 & 31;
        int r = idxrow[kb + kr];
        cp16(smem_u32 + (uint32_t)(W_OFF + buf * WBUF + kr * WP) * 8 + seg * 16,
             wbase + (size_t)r * CDIM + c0 + seg * 2);
    }
    asm volatile("cp.async.commit_group;");
}

__global__ void __launch_bounds__(K2_THREADS) out_tc_kernel(
    const int* __restrict__ idx, float* __restrict__ out)
{
    extern __shared__ float2 sm2[];
    int* idxrow = (int*)((char*)sm2 + IDX_OFF);
    const int q = blockIdx.y;
    const int c0 = blockIdx.x * 64;
    const int tid = threadIdx.x;
    const int lane = tid & 31;
    const int wid = tid >> 5;
    const int mp = wid >> 1, nh = wid & 1;

    uint32_t smem_u32;
    asm("{ .reg .u64 t; cvta.to.shared.u64 t, %1; cvt.u32.u64 %0, t; }"
        : "=r"(smem_u32) : "l"(sm2));

    for (int i = tid; i < KPAD; i += K2_THREADS)
        idxrow[i] = (i < LK) ? idx[q * LK + i] : 0;
    __syncthreads();

    float c[2][4][4];
#pragma unroll
    for (int a = 0; a < 2; a++)
#pragma unroll
        for (int b = 0; b < 4; b++)
#pragma unroll
            for (int d = 0; d < 4; d++) c[a][b][d] = 0.f;

    k2_load(q, c0, tid, smem_u32, idxrow, 0);

    const int rA0 = mp * 32 + (lane >> 2);
    for (int i = 0; i < 14; i++) {
        asm volatile("cp.async.wait_group 0;");
        __syncthreads();
        if (i + 1 < 14) k2_load(q, c0, tid, smem_u32, idxrow, i + 1);

        const float2* Af = sm2 + A_OFF + (i & 1) * ABUF;
        const float2* Wf = sm2 + W_OFF + (i & 1) * WBUF;
#pragma unroll
        for (int kc = 0; kc < 4; kc++) {
            const int kcol = kc * 8 + (lane & 3);
            float2 a00 = Af[(rA0)      * AP + kcol];
            float2 a01 = Af[(rA0 + 8)  * AP + kcol];
            float2 a02 = Af[(rA0)      * AP + kcol + 4];
            float2 a03 = Af[(rA0 + 8)  * AP + kcol + 4];
            float2 a10 = Af[(rA0 + 16) * AP + kcol];
            float2 a11 = Af[(rA0 + 24) * AP + kcol];
            float2 a12 = Af[(rA0 + 16) * AP + kcol + 4];
            float2 a13 = Af[(rA0 + 24) * AP + kcol + 4];
#pragma unroll
            for (int nt = 0; nt < 4; nt++) {
                const int ncol = (nh * 4 + nt) * 8 + (lane >> 2);
                float2 b0 = Wf[kcol * WP + ncol];
                float2 b1 = Wf[(kcol + 4) * WP + ncol];
                mma8(c[0][nt], U(a00.x), U(a01.x), U(a02.x), U(a03.x), U(b0.x), U(b1.x));
                mma8(c[0][nt], U(a00.y), U(a01.y), U(a02.y), U(a03.y), U(b0.x), U(b1.x));
                mma8(c[0][nt], U(a00.x), U(a01.x), U(a02.x), U(a03.x), U(b0.y), U(b1.y));
                mma8(c[1][nt], U(a10.x), U(a11.x), U(a12.x), U(a13.x), U(b0.x), U(b1.x));
                mma8(c[1][nt], U(a10.y), U(a11.y), U(a12.y), U(a13.y), U(b0.x), U(b1.x));
                mma8(c[1][nt], U(a10.x), U(a11.x), U(a12.x), U(a13.x), U(b0.y), U(b1.y));
            }
        }
    }

#pragma unroll
    for (int mt = 0; mt < 2; mt++) {
#pragma unroll
        for (int nt = 0; nt < 4; nt++) {
            int mrow = mp * 32 + mt * 16 + (lane >> 2);
            int col = c0 + (nh * 4 + nt) * 8 + 2 * (lane & 3);
            float* ob0 = out + ((size_t)mrow * LL + q + 1) * CDIM + col;
            float* ob1 = out + ((size_t)(mrow + 8) * LL + q + 1) * CDIM + col;
            *(float2*)ob0 = make_float2(c[mt][nt][0], c[mt][nt][1]);
            *(float2*)ob1 = make_float2(c[mt][nt][2], c[mt][nt][3]);
        }
    }
}

// ===========================================================================
// prep: split w1/w2 -> f2;  zero the l=0 slice of out
// ===========================================================================
__global__ void wsplit_kernel(const float* __restrict__ w1,
                              const float* __restrict__ w2)
{
    int i = blockIdx.x * blockDim.x + threadIdx.x;
    const int n1 = WSZ * CDIM;
    if (i < 2 * n1) {
        int sel = i >= n1;
        int j = i - sel * n1;
        float x = sel ? w2[j] : w1[j];
        uint32_t hi, lo; split_tf32(x, hi, lo);
        float2 v = make_float2(__uint_as_float(hi), __uint_as_float(lo));
        if (sel) g_w2s[j] = v; else g_w1s[j] = v;
    }
}

__global__ void zero_l0_kernel(float* __restrict__ out) {
    int i = blockIdx.x * blockDim.x + threadIdx.x;   // 128*768
    int nt = i / CDIM, cc = i - nt * CDIM;
    out[(size_t)nt * LL * CDIM + cc] = 0.f;
}

extern "C" void kernel_launch(void* const* d_in, const int* in_sizes, int n_in,
                              void* d_out, int out_size)
{
    const float* q  = (const float*)d_in[0];
    const float* k  = (const float*)d_in[1];
    const float* w1 = (const float*)d_in[2];
    const float* w2 = (const float*)d_in[3];
    const int*  idx = (const int*)d_in[4];
    float* out = (float*)d_out;

    cudaFuncSetAttribute(attn_tc_kernel, cudaFuncAttributeMaxDynamicSharedMemorySize, SMEM1_BYTES);
    cudaFuncSetAttribute(out_tc_kernel, cudaFuncAttributeMaxDynamicSharedMemorySize, SMEM2_BYTES);

    wsplit_kernel<<<(2 * WSZ * CDIM + 255) / 256, 256>>>(w1, w2);
    attn_tc_kernel<<<dim3(2, NPAIR, 2), K1_THREADS, SMEM1_BYTES>>>(q, k);
    zero_l0_kernel<<<96, 1024>>>(out);
    out_tc_kernel<<<dim3(12, LK), K2_THREADS, SMEM2_BYTES>>>(idx, out);
}

// round 5
// speedup vs baseline: 1.4884x; 1.4884x over previous
#include <cuda_runtime.h>
#include <cstdint>

#define TT    8
#define LL    197
#define HH    12
#define DD    64
#define LK    196
#define NPAIR 112
#define CDIM  768
#define KPAD  224

// attn scratch, packed bf16 (hi,lo) fragment words: [half][q 196][pair 112][224 words]
__device__ uint32_t g_attn2[2u * LK * NPAIR * KPAD];
// zero source for cp.async of invalid rows
__device__ ulonglong2 g_zero4[16];

__device__ __forceinline__ void cp16(uint32_t dst, const void* src) {
    asm volatile("cp.async.cg.shared.global [%0], [%1], 16;" :: "r"(dst), "l"(src));
}
__device__ __forceinline__ float trunc16(float x) {
    return __uint_as_float(__float_as_uint(x) & 0xffff0000u);
}
__device__ __forceinline__ uint32_t packhi(float a, float b) {
    return __byte_perm(__float_as_uint(a), __float_as_uint(b), 0x7632);
}
__device__ __forceinline__ void split_tf32(float x, uint32_t& hi, uint32_t& lo) {
    uint32_t h;
    asm("cvt.rna.tf32.f32 %0, %1;" : "=r"(h) : "f"(x));
    float lf = x - __uint_as_float(h);
    uint32_t l;
    asm("cvt.rna.tf32.f32 %0, %1;" : "=r"(l) : "f"(lf));
    hi = h; lo = l;
}
__device__ __forceinline__ void mma_tf32(float* c,
    uint32_t a0, uint32_t a1, uint32_t a2, uint32_t a3, uint32_t b0, uint32_t b1)
{
    asm volatile("mma.sync.aligned.m16n8k8.row.col.f32.tf32.tf32.f32 "
        "{%0,%1,%2,%3},{%4,%5,%6,%7},{%8,%9},{%0,%1,%2,%3};"
        : "+f"(c[0]), "+f"(c[1]), "+f"(c[2]), "+f"(c[3])
        : "r"(a0), "r"(a1), "r"(a2), "r"(a3), "r"(b0), "r"(b1));
}
__device__ __forceinline__ void mma_bf16(float* c,
    uint32_t a0, uint32_t a1, uint32_t a2, uint32_t a3, uint32_t b0, uint32_t b1)
{
    asm volatile("mma.sync.aligned.m16n8k16.row.col.f32.bf16.bf16.f32 "
        "{%0,%1,%2,%3},{%4,%5,%6,%7},{%8,%9},{%0,%1,%2,%3};"
        : "+f"(c[0]), "+f"(c[1]), "+f"(c[2]), "+f"(c[3])
        : "r"(a0), "r"(a1), "r"(a2), "r"(a3), "r"(b0), "r"(b1));
}

// ===========================================================================
// Kernel 1: tf32 tensor-core scores + softmax + mean over heads (R3 body)
// grid (2 qtiles, 112 pairs, 2 halves), 448 threads = 14 warps
// epilogue packs mean into bf16 (hi,lo) fragment words -> g_attn2
// ===========================================================================
#define K1_THREADS 448
#define QROWS 112
#define KROWS 200
#define PITCH 68

#define QS_OFF   0
#define KS_OFF   (2 * QROWS * PITCH)
#define RED_OFF  (KS_OFF + 2 * KROWS * PITCH)
#define REDSUM_OFF (RED_OFF + 2 * QROWS)
#define SMEM1_FLOATS (REDSUM_OFF + 2 * QROWS)
#define SMEM1_BYTES (SMEM1_FLOATS * 4)

__device__ __forceinline__ void load_head(
    const float* __restrict__ q, const float* __restrict__ k,
    size_t qbase, size_t kbase, int q0, int tid, uint32_t smem_u32,
    int h, int buf)
{
#pragma unroll
    for (int it = 0; it < 4; it++) {
        int i = tid + it * K1_THREADS;
        int row = i >> 4, c4 = i & 15;
        int qg = q0 + row; if (qg > 195) qg = 195;
        const float* src = q + qbase + (size_t)qg * (HH * DD) + h * DD + c4 * 4;
        cp16(smem_u32 + (uint32_t)(QS_OFF + (buf * QROWS + row) * PITCH + c4 * 4) * 4, src);
    }
#pragma unroll
    for (int it = 0; it < 8; it++) {
        int i = tid + it * K1_THREADS;
        if (i < KROWS * 16) {
            int row = i >> 4, c4 = i & 15;
            int kg = row > 195 ? 195 : row;
            const float* src = k + kbase + (size_t)kg * (HH * DD) + h * DD + c4 * 4;
            cp16(smem_u32 + (uint32_t)(KS_OFF + (buf * KROWS + row) * PITCH + c4 * 4) * 4, src);
        }
    }
    asm volatile("cp.async.commit_group;");
}

__global__ void __launch_bounds__(K1_THREADS, 1) attn_tc_kernel(
    const float* __restrict__ q, const float* __restrict__ k)
{
    extern __shared__ float sm[];
    const int tid = threadIdx.x;
    const int lane = tid & 31;
    const int wid = tid >> 5;
    const int stripe = wid >> 1;
    const int nhalf = wid & 1;
    const int r0 = stripe * 16;
    const int qt = blockIdx.x;
    const int p = blockIdx.y;
    const int hf = blockIdx.z;
    const int n = p / 7, tp = p % 7;
    const int tq = (hf == 0) ? tp + 1 : tp;
    const int tk = (hf == 0) ? tp : tp + 1;
    const size_t qbase = ((size_t)(n * TT + tq) * LL + 1) * (HH * DD);
    const size_t kbase = ((size_t)(n * TT + tk) * LL + 1) * (HH * DD);
    const int q0 = qt * QROWS;

    uint32_t smem_u32;
    asm("{ .reg .u64 t; cvta.to.shared.u64 t, %1; cvt.u32.u64 %0, t; }"
        : "=r"(smem_u32) : "l"(sm));

    const int nt0 = nhalf ? 13 : 0;
    const int cnt = nhalf ? 12 : 13;
    const int rA = r0 + (lane >> 2);
    const int rB = rA + 8;

    float macc[13][4];
#pragma unroll
    for (int t = 0; t < 13; t++)
#pragma unroll
        for (int j = 0; j < 4; j++) macc[t][j] = 0.f;

    load_head(q, k, qbase, kbase, q0, tid, smem_u32, 0, 0);
    asm volatile("cp.async.wait_group 0;");
    __syncthreads();

    for (int h = 0; h < HH; h++) {
        const int buf = h & 1;
        if (h + 1 < HH) load_head(q, k, qbase, kbase, q0, tid, smem_u32, h + 1, buf ^ 1);

        const float* qs = sm + QS_OFF + buf * QROWS * PITCH;
        const float* ks = sm + KS_OFF + buf * KROWS * PITCH;

        float c[13][4];
#pragma unroll
        for (int t = 0; t < 13; t++)
#pragma unroll
            for (int j = 0; j < 4; j++) c[t][j] = 0.f;

#pragma unroll
        for (int kc = 0; kc < 8; kc++) {
            const int dcol = kc * 8 + (lane & 3);
            float a0f = qs[rA * PITCH + dcol];
            float a1f = qs[rB * PITCH + dcol];
            float a2f = qs[rA * PITCH + dcol + 4];
            float a3f = qs[rB * PITCH + dcol + 4];
            uint32_t ah0, al0, ah1, al1, ah2, al2, ah3, al3;
            split_tf32(a0f, ah0, al0);
            split_tf32(a1f, ah1, al1);
            split_tf32(a2f, ah2, al2);
            split_tf32(a3f, ah3, al3);
#pragma unroll
            for (int t = 0; t < 13; t++) {
                if (t < cnt) {
                    const int nt = nt0 + t;
                    const int brow = nt * 8 + (lane >> 2);
                    float b0f = ks[brow * PITCH + dcol];
                    float b1f = ks[brow * PITCH + dcol + 4];
                    uint32_t bh0, bl0, bh1, bl1;
                    split_tf32(b0f, bh0, bl0);
                    split_tf32(b1f, bh1, bl1);
                    mma_tf32(c[t], ah0, ah1, ah2, ah3, bh0, bh1);
                    mma_tf32(c[t], al0, al1, al2, al3, bh0, bh1);
                    mma_tf32(c[t], ah0, ah1, ah2, ah3, bl0, bl1);
                }
            }
        }

        if (nhalf && (lane & 3) >= 2) {
            c[11][0] = -1e30f; c[11][1] = -1e30f;
            c[11][2] = -1e30f; c[11][3] = -1e30f;
        }

        float mA = -1e30f, mB = -1e30f;
#pragma unroll
        for (int t = 0; t < 13; t++) {
            if (t < cnt) {
                mA = fmaxf(mA, fmaxf(c[t][0], c[t][1]));
                mB = fmaxf(mB, fmaxf(c[t][2], c[t][3]));
            }
        }
#pragma unroll
        for (int o = 1; o <= 2; o <<= 1) {
            mA = fmaxf(mA, __shfl_xor_sync(0xffffffffu, mA, o));
            mB = fmaxf(mB, __shfl_xor_sync(0xffffffffu, mB, o));
        }
        if ((lane & 3) == 0) {
            sm[RED_OFF + rA * 2 + nhalf] = mA;
            sm[RED_OFF + rB * 2 + nhalf] = mB;
        }
        __syncthreads();
        mA = fmaxf(mA, sm[RED_OFF + rA * 2 + (1 - nhalf)]);
        mB = fmaxf(mB, sm[RED_OFF + rB * 2 + (1 - nhalf)]);

        float sA = 0.f, sB = 0.f;
#pragma unroll
        for (int t = 0; t < 13; t++) {
            if (t < cnt) {
                c[t][0] = __expf((c[t][0] - mA) * 0.125f);
                c[t][1] = __expf((c[t][1] - mA) * 0.125f);
                c[t][2] = __expf((c[t][2] - mB) * 0.125f);
                c[t][3] = __expf((c[t][3] - mB) * 0.125f);
                sA += c[t][0] + c[t][1];
                sB += c[t][2] + c[t][3];
            }
        }
#pragma unroll
        for (int o = 1; o <= 2; o <<= 1) {
            sA += __shfl_xor_sync(0xffffffffu, sA, o);
            sB += __shfl_xor_sync(0xffffffffu, sB, o);
        }
        if ((lane & 3) == 0) {
            sm[REDSUM_OFF + rA * 2 + nhalf] = sA;
            sm[REDSUM_OFF + rB * 2 + nhalf] = sB;
        }
        __syncthreads();
        sA += sm[REDSUM_OFF + rA * 2 + (1 - nhalf)];
        sB += sm[REDSUM_OFF + rB * 2 + (1 - nhalf)];
        const float iA = 1.0f / (12.0f * sA);
        const float iB = 1.0f / (12.0f * sB);
#pragma unroll
        for (int t = 0; t < 13; t++) {
            if (t < cnt) {
                macc[t][0] += c[t][0] * iA;
                macc[t][1] += c[t][1] * iA;
                macc[t][2] += c[t][2] * iB;
                macc[t][3] += c[t][3] * iB;
            }
        }

        if (h + 1 < HH) asm volatile("cp.async.wait_group 0;");
        __syncthreads();
    }

    // epilogue: pack mean into bf16 (hi,lo) fragment words
    // word layout per row: kcg*16 + j*4 + plane*2 + h, col = kcg*16 + h*8 + 2j
    uint32_t* stg = (uint32_t*)(sm + KS_OFF);   // [112][KPAD]
    for (int i = tid; i < QROWS * KPAD; i += K1_THREADS) stg[i] = 0u;
    __syncthreads();
#pragma unroll
    for (int t = 0; t < 13; t++) {
        if (t < cnt) {
            const int col0 = (nt0 + t) * 8 + 2 * (lane & 3);
            const int kcg = col0 >> 4, rem = col0 & 15;
            const int wp = kcg * 16 + ((rem >> 1) & 3) * 4 + (rem >> 3);
            {
                uint32_t hw = packhi(macc[t][0], macc[t][1]);
                float l0 = macc[t][0] - trunc16(macc[t][0]);
                float l1 = macc[t][1] - trunc16(macc[t][1]);
                uint32_t lw = packhi(l0, l1);
                stg[rA * KPAD + wp] = hw;
                stg[rA * KPAD + wp + 2] = lw;
            }
            {
                uint32_t hw = packhi(macc[t][2], macc[t][3]);
                float l0 = macc[t][2] - trunc16(macc[t][2]);
                float l1 = macc[t][3] - trunc16(macc[t][3]);
                uint32_t lw = packhi(l0, l1);
                stg[rB * KPAD + wp] = hw;
                stg[rB * KPAD + wp + 2] = lw;
            }
        }
    }
    __syncthreads();
    for (int i = tid; i < QROWS * 56; i += K1_THREADS) {
        int row = i / 56, s4 = i % 56;
        int qg = q0 + row;
        if (qg < LK) {
            uint4 v = *((const uint4*)(stg + row * KPAD) + s4);
            *((uint4*)(g_attn2 + ((size_t)(hf * LK + qg) * NPAIR + p) * KPAD) + s4) = v;
        }
    }
}

// ===========================================================================
// Kernel 2: out = attn @ Wgather, bf16 2-term split, m16n8k16
// grid (6 c-tiles of 128, 196 q), 256 threads = 8 warps (2 mg x 4 ng)
// smem words: A[2][128][48] | W[2][128][48] (raw W staged in-place) | idx
// ===========================================================================
#define K2_THREADS 256
#define AW 6144
#define A_OFF 0
#define W_OFF (2 * AW)
#define IDXW (4 * AW)
#define SMEM2_BYTES ((IDXW + KPAD) * 4)

__device__ __forceinline__ void k2_load(
    int q, int c0, int tid, uint32_t smem_u32,
    const float* __restrict__ w1, const float* __restrict__ w2,
    const int* __restrict__ idxrow, int s)
{
    const int half = s / 7;
    const int kb = (s % 7) * 32;
    const int buf = s & 1;
    // A: 128 rows x 8 cp16 (packed words, direct from g_attn2)
#pragma unroll
    for (int t = 0; t < 4; t++) {
        int id = tid + t * K2_THREADS;
        int row = id >> 3, seg = id & 7;
        int nn = row >> 3, tt = row & 7;
        const void* src;
        if (half == 0) {
            src = (tt >= 1) ? (const void*)(g_attn2 +
                    ((size_t)q * NPAIR + nn * 7 + tt - 1) * KPAD + kb + seg * 4)
                            : (const void*)((const char*)g_zero4 + seg * 16);
        } else {
            src = (tt <= 6) ? (const void*)(g_attn2 +
                    ((size_t)(LK + q) * NPAIR + nn * 7 + tt) * KPAD + kb + seg * 4)
                            : (const void*)((const char*)g_zero4 + seg * 16);
        }
        cp16(smem_u32 + (uint32_t)(A_OFF + buf * AW + row * 48 + seg * 4) * 4, src);
    }
    // W raw: 32 rows x 32 cp16 (128 floats per gathered row)
    const float* wb = half ? w2 : w1;
#pragma unroll
    for (int t = 0; t < 4; t++) {
        int id = tid + t * K2_THREADS;
        int kr = id >> 5, seg = id & 31;
        int r = idxrow[kb + kr];
        cp16(smem_u32 + (uint32_t)(W_OFF + buf * AW + kr * 128 + seg * 4) * 4,
             wb + (size_t)r * CDIM + c0 + seg * 4);
    }
    asm volatile("cp.async.commit_group;");
}

__global__ void __launch_bounds__(K2_THREADS, 2) out_tc_kernel(
    const float* __restrict__ w1, const float* __restrict__ w2,
    const int* __restrict__ idx, float* __restrict__ out)
{
    extern __shared__ uint32_t smw[];
    int* idxrow = (int*)(smw + IDXW);
    const int q = blockIdx.y;
    const int c0 = blockIdx.x * 128;
    const int tid = threadIdx.x;
    const int lane = tid & 31;
    const int wid = tid >> 5;
    const int mg = wid >> 2, ng = wid & 3;
    const int laneq = lane >> 2, lane4 = lane & 3;

    uint32_t smem_u32;
    asm("{ .reg .u64 t; cvta.to.shared.u64 t, %1; cvt.u32.u64 %0, t; }"
        : "=r"(smem_u32) : "l"(smw));

    for (int i = tid; i < KPAD; i += K2_THREADS)
        idxrow[i] = (i < LK) ? idx[q * LK + i] : 0;
    __syncthreads();

    float acc[4][4][4];
#pragma unroll
    for (int a = 0; a < 4; a++)
#pragma unroll
        for (int b = 0; b < 4; b++)
#pragma unroll
            for (int d = 0; d < 4; d++) acc[a][b][d] = 0.f;

    k2_load(q, c0, tid, smem_u32, w1, w2, idxrow, 0);

    for (int s = 0; s < 14; s++) {
        const int buf = s & 1;
        if (s + 1 < 14) {
            k2_load(q, c0, tid, smem_u32, w1, w2, idxrow, s + 1);
            asm volatile("cp.async.wait_group 1;");
        } else {
            asm volatile("cp.async.wait_group 0;");
        }
        __syncthreads();

        // W convert: raw [k 32][c 128] f32 -> packed [c][48] words, in place
        float f[4][4];
        int cc[4], ckc[4], cj[4];
#pragma unroll
        for (int t = 0; t < 4; t++) {
            int id = tid + t * K2_THREADS;
            cc[t] = id & 127;
            int kcj = id >> 7;
            ckc[t] = kcj >> 2; cj[t] = kcj & 3;
            int k0 = ckc[t] * 16 + 2 * cj[t];
            const float* wr = (const float*)(smw + W_OFF + buf * AW);
            f[t][0] = wr[k0 * 128 + cc[t]];
            f[t][1] = wr[(k0 + 1) * 128 + cc[t]];
            f[t][2] = wr[(k0 + 8) * 128 + cc[t]];
            f[t][3] = wr[(k0 + 9) * 128 + cc[t]];
        }
        __syncthreads();
#pragma unroll
        for (int t = 0; t < 4; t++) {
            uint4 v;
            v.x = packhi(f[t][0], f[t][1]);
            v.y = packhi(f[t][2], f[t][3]);
            float r0 = f[t][0] - trunc16(f[t][0]);
            float r1 = f[t][1] - trunc16(f[t][1]);
            float r2 = f[t][2] - trunc16(f[t][2]);
            float r3 = f[t][3] - trunc16(f[t][3]);
            v.z = packhi(r0, r1);
            v.w = packhi(r2, r3);
            *(uint4*)(smw + W_OFF + buf * AW + cc[t] * 48 + ckc[t] * 16 + cj[t] * 4) = v;
        }
        __syncthreads();

        // MMA
        const uint32_t* Ab = smw + A_OFF + buf * AW + (mg * 64 + laneq) * 48 + lane4 * 4;
        const uint32_t* Bb = smw + W_OFF + buf * AW + (ng * 32 + laneq) * 48 + lane4 * 4;
#pragma unroll
        for (int kc = 0; kc < 2; kc++) {
            uint4 bw[4];
#pragma unroll
            for (int nt = 0; nt < 4; nt++)
                bw[nt] = *(const uint4*)(Bb + nt * 8 * 48 + kc * 16);
#pragma unroll
            for (int mt = 0; mt < 4; mt++) {
                uint4 a0 = *(const uint4*)(Ab + mt * 16 * 48 + kc * 16);
                uint4 a1 = *(const uint4*)(Ab + (mt * 16 + 8) * 48 + kc * 16);
#pragma unroll
                for (int nt = 0; nt < 4; nt++) {
                    mma_bf16(acc[mt][nt], a0.x, a1.x, a0.y, a1.y, bw[nt].x, bw[nt].y);
                    mma_bf16(acc[mt][nt], a0.z, a1.z, a0.w, a1.w, bw[nt].x, bw[nt].y);
                    mma_bf16(acc[mt][nt], a0.x, a1.x, a0.y, a1.y, bw[nt].z, bw[nt].w);
                }
            }
        }
        __syncthreads();
    }

    // epilogue
#pragma unroll
    for (int mt = 0; mt < 4; mt++) {
#pragma unroll
        for (int nt = 0; nt < 4; nt++) {
            int mrow = mg * 64 + mt * 16 + laneq;
            int col = c0 + ng * 32 + nt * 8 + 2 * lane4;
            float* ob0 = out + ((size_t)mrow * LL + q + 1) * CDIM + col;
            float* ob1 = out + ((size_t)(mrow + 8) * LL + q + 1) * CDIM + col;
            *(float2*)ob0 = make_float2(acc[mt][nt][0], acc[mt][nt][1]);
            *(float2*)ob1 = make_float2(acc[mt][nt][2], acc[mt][nt][3]);
        }
    }
}

__global__ void zero_l0_kernel(float* __restrict__ out) {
    int i = blockIdx.x * blockDim.x + threadIdx.x;   // 128*768
    int nt = i / CDIM, cc = i - nt * CDIM;
    out[(size_t)nt * LL * CDIM + cc] = 0.f;
}

extern "C" void kernel_launch(void* const* d_in, const int* in_sizes, int n_in,
                              void* d_out, int out_size)
{
    const float* q  = (const float*)d_in[0];
    const float* k  = (const float*)d_in[1];
    const float* w1 = (const float*)d_in[2];
    const float* w2 = (const float*)d_in[3];
    const int*  idx = (const int*)d_in[4];
    float* out = (float*)d_out;

    cudaFuncSetAttribute(attn_tc_kernel, cudaFuncAttributeMaxDynamicSharedMemorySize, SMEM1_BYTES);
    cudaFuncSetAttribute(out_tc_kernel, cudaFuncAttributeMaxDynamicSharedMemorySize, SMEM2_BYTES);

    attn_tc_kernel<<<dim3(2, NPAIR, 2), K1_THREADS, SMEM1_BYTES>>>(q, k);
    zero_l0_kernel<<<96, 1024>>>(out);
    out_tc_kernel<<<dim3(6, LK), K2_THREADS, SMEM2_BYTES>>>(w1, w2, idx, out);
}

// round 6
// speedup vs baseline: 2.0479x; 1.3759x over previous
#include <cuda_runtime.h>
#include <cstdint>

#define TT    8
#define LL    197
#define HH    12
#define DD    64
#define LK    196
#define NPAIR 112
#define CDIM  768
#define KPAD  224

// attn scratch, packed bf16 (hi,lo) fragment words: [half][q 196][pair 112][224 words]
__device__ uint32_t g_attn2[2u * LK * NPAIR * KPAD];
// zero source for cp.async of invalid rows
__device__ ulonglong2 g_zero4[16];

__device__ __forceinline__ void cp16(uint32_t dst, const void* src) {
    asm volatile("cp.async.cg.shared.global [%0], [%1], 16;" :: "r"(dst), "l"(src));
}
__device__ __forceinline__ float trunc16(float x) {
    return __uint_as_float(__float_as_uint(x) & 0xffff0000u);
}
__device__ __forceinline__ uint32_t packhi(float a, float b) {
    return __byte_perm(__float_as_uint(a), __float_as_uint(b), 0x7632);
}
__device__ __forceinline__ void mma_bf16(float* c,
    uint32_t a0, uint32_t a1, uint32_t a2, uint32_t a3, uint32_t b0, uint32_t b1)
{
    asm volatile("mma.sync.aligned.m16n8k16.row.col.f32.bf16.bf16.f32 "
        "{%0,%1,%2,%3},{%4,%5,%6,%7},{%8,%9},{%0,%1,%2,%3};"
        : "+f"(c[0]), "+f"(c[1]), "+f"(c[2]), "+f"(c[3])
        : "r"(a0), "r"(a1), "r"(a2), "r"(a3), "r"(b0), "r"(b1));
}

// ===========================================================================
// Kernel 1: bf16 2-term split tensor-core scores + softmax + head-mean
// grid (2 qtiles, 112 pairs, 2 halves), 448 threads = 14 warps
// warp = (stripe 0..6 [m16], nhalf 0..1 [13 or 12 n-tiles of 8])
// smem words: QP 112x80 | KP 200x80 | QR 112x64 | KR 200x64 | RED 2x224
// ===========================================================================
#define K1_THREADS 448
#define QROWS 112
#define KROWS 200
#define PW    80
#define QP_OFF 0
#define KP_OFF (QROWS * PW)             // 8960
#define QR_OFF (KP_OFF + KROWS * PW)    // 24960
#define KR_OFF (QR_OFF + QROWS * 64)    // 32128
#define RED1_OFF (KR_OFF + KROWS * 64)  // 44928
#define RED2_OFF (RED1_OFF + 224)
#define SMEM1_WORDS (RED2_OFF + 224)    // 45376
#define SMEM1_BYTES (SMEM1_WORDS * 4)   // 181504

__device__ __forceinline__ void k1_load_raw(
    const float* __restrict__ q, const float* __restrict__ k,
    size_t qbase, size_t kbase, int q0, int tid, uint32_t smem_u32, int h)
{
    // Q: 112 rows x 16 cp16
#pragma unroll
    for (int it = 0; it < 4; it++) {
        int i = tid + it * K1_THREADS;
        int row = i >> 4, c4 = i & 15;
        int qg = q0 + row; if (qg > 195) qg = 195;
        const float* src = q + qbase + (size_t)qg * (HH * DD) + h * DD + c4 * 4;
        cp16(smem_u32 + (uint32_t)(QR_OFF + row * 64 + c4 * 4) * 4, src);
    }
    // K: 200 rows x 16 cp16
#pragma unroll
    for (int it = 0; it < 8; it++) {
        int i = tid + it * K1_THREADS;
        if (i < KROWS * 16) {
            int row = i >> 4, c4 = i & 15;
            int kg = row > 195 ? 195 : row;
            const float* src = k + kbase + (size_t)kg * (HH * DD) + h * DD + c4 * 4;
            cp16(smem_u32 + (uint32_t)(KR_OFF + row * 64 + c4 * 4) * 4, src);
        }
    }
    asm volatile("cp.async.commit_group;");
}

__global__ void __launch_bounds__(K1_THREADS, 1) attn_tc_kernel(
    const float* __restrict__ q, const float* __restrict__ k)
{
    extern __shared__ float sm[];
    uint32_t* smw = (uint32_t*)sm;
    const int tid = threadIdx.x;
    const int lane = tid & 31;
    const int wid = tid >> 5;
    const int stripe = wid >> 1;
    const int nhalf = wid & 1;
    const int laneq = lane >> 2, lane4 = lane & 3;
    const int qt = blockIdx.x;
    const int p = blockIdx.y;
    const int hf = blockIdx.z;
    const int n = p / 7, tp = p % 7;
    const int tq = (hf == 0) ? tp + 1 : tp;
    const int tk = (hf == 0) ? tp : tp + 1;
    const size_t qbase = ((size_t)(n * TT + tq) * LL + 1) * (HH * DD);
    const size_t kbase = ((size_t)(n * TT + tk) * LL + 1) * (HH * DD);
    const int q0 = qt * QROWS;

    uint32_t smem_u32;
    asm("{ .reg .u64 t; cvta.to.shared.u64 t, %1; cvt.u32.u64 %0, t; }"
        : "=r"(smem_u32) : "l"(sm));

    const int nt0 = nhalf ? 13 : 0;
    const int cnt = nhalf ? 12 : 13;
    const int rA = stripe * 16 + laneq;
    const int rB = rA + 8;

    float macc[13][4];
#pragma unroll
    for (int t = 0; t < 13; t++)
#pragma unroll
        for (int j = 0; j < 4; j++) macc[t][j] = 0.f;

    k1_load_raw(q, k, qbase, kbase, q0, tid, smem_u32, 0);
    asm volatile("cp.async.wait_group 0;");
    __syncthreads();

    for (int h = 0; h < HH; h++) {
        // ---- convert raw fp32 -> packed bf16 (hi,lo) fragment words ----
        // output-centric: each thread builds one packed uint4 per iter
#pragma unroll
        for (int it = 0; it < 12; it++) {
            int i = tid + it * K1_THREADS;
            if (i < (QROWS + KROWS) * 16) {
                int srcb, dstb, r, sub;
                if (i < QROWS * 16) {
                    r = i >> 4; sub = i & 15;
                    srcb = QR_OFF + r * 64;
                    dstb = QP_OFF + r * PW;
                } else {
                    int j = i - QROWS * 16;
                    r = j >> 4; sub = j & 15;
                    srcb = KR_OFF + r * 64;
                    dstb = KP_OFF + r * PW;
                }
                const int kcg = sub >> 2, l4 = sub & 3;
                const int d0 = kcg * 16 + 2 * l4;
                float2 pA = *(const float2*)(sm + srcb + d0);
                float2 pB = *(const float2*)(sm + srcb + d0 + 8);
                uint4 v;
                v.x = packhi(pA.x, pA.y);
                v.y = packhi(pB.x, pB.y);
                v.z = packhi(pA.x - trunc16(pA.x), pA.y - trunc16(pA.y));
                v.w = packhi(pB.x - trunc16(pB.x), pB.y - trunc16(pB.y));
                *(uint4*)(smw + dstb + kcg * 16 + l4 * 4) = v;
            }
        }
        __syncthreads();
        if (h + 1 < HH) k1_load_raw(q, k, qbase, kbase, q0, tid, smem_u32, h + 1);

        // ---- MMA: scores for this head ----
        float c[13][4];
#pragma unroll
        for (int t = 0; t < 13; t++)
#pragma unroll
            for (int j = 0; j < 4; j++) c[t][j] = 0.f;

#pragma unroll
        for (int kcg = 0; kcg < 4; kcg++) {
            uint4 aA = *(const uint4*)(smw + QP_OFF + rA * PW + kcg * 16 + lane4 * 4);
            uint4 aB = *(const uint4*)(smw + QP_OFF + rB * PW + kcg * 16 + lane4 * 4);
#pragma unroll
            for (int t = 0; t < 13; t++) {
                if (t < cnt) {
                    const int brow = (nt0 + t) * 8 + laneq;
                    uint4 bw = *(const uint4*)(smw + KP_OFF + brow * PW + kcg * 16 + lane4 * 4);
                    mma_bf16(c[t], aA.x, aB.x, aA.y, aB.y, bw.x, bw.y);
                    mma_bf16(c[t], aA.z, aB.z, aA.w, aB.w, bw.x, bw.y);
                    mma_bf16(c[t], aA.x, aB.x, aA.y, aB.y, bw.z, bw.w);
                }
            }
        }

        // mask invalid n cols 196..199 (n-tile 24: nhalf warp, local t==11)
        if (nhalf && lane4 >= 2) {
            c[11][0] = -1e30f; c[11][1] = -1e30f;
            c[11][2] = -1e30f; c[11][3] = -1e30f;
        }

        // ---- softmax (rows rA, rB) + head-mean accumulation ----
        float mA = -1e30f, mB = -1e30f;
#pragma unroll
        for (int t = 0; t < 13; t++) {
            if (t < cnt) {
                mA = fmaxf(mA, fmaxf(c[t][0], c[t][1]));
                mB = fmaxf(mB, fmaxf(c[t][2], c[t][3]));
            }
        }
#pragma unroll
        for (int o = 1; o <= 2; o <<= 1) {
            mA = fmaxf(mA, __shfl_xor_sync(0xffffffffu, mA, o));
            mB = fmaxf(mB, __shfl_xor_sync(0xffffffffu, mB, o));
        }
        if (lane4 == 0) {
            sm[RED1_OFF + rA * 2 + nhalf] = mA;
            sm[RED1_OFF + rB * 2 + nhalf] = mB;
        }
        __syncthreads();
        mA = fmaxf(mA, sm[RED1_OFF + rA * 2 + (1 - nhalf)]);
        mB = fmaxf(mB, sm[RED1_OFF + rB * 2 + (1 - nhalf)]);

        float sA = 0.f, sB = 0.f;
#pragma unroll
        for (int t = 0; t < 13; t++) {
            if (t < cnt) {
                c[t][0] = __expf((c[t][0] - mA) * 0.125f);
                c[t][1] = __expf((c[t][1] - mA) * 0.125f);
                c[t][2] = __expf((c[t][2] - mB) * 0.125f);
                c[t][3] = __expf((c[t][3] - mB) * 0.125f);
                sA += c[t][0] + c[t][1];
                sB += c[t][2] + c[t][3];
            }
        }
#pragma unroll
        for (int o = 1; o <= 2; o <<= 1) {
            sA += __shfl_xor_sync(0xffffffffu, sA, o);
            sB += __shfl_xor_sync(0xffffffffu, sB, o);
        }
        if (lane4 == 0) {
            sm[RED2_OFF + rA * 2 + nhalf] = sA;
            sm[RED2_OFF + rB * 2 + nhalf] = sB;
        }
        __syncthreads();
        sA += sm[RED2_OFF + rA * 2 + (1 - nhalf)];
        sB += sm[RED2_OFF + rB * 2 + (1 - nhalf)];
        const float iA = 1.0f / (12.0f * sA);
        const float iB = 1.0f / (12.0f * sB);
#pragma unroll
        for (int t = 0; t < 13; t++) {
            if (t < cnt) {
                macc[t][0] += c[t][0] * iA;
                macc[t][1] += c[t][1] * iA;
                macc[t][2] += c[t][2] * iB;
                macc[t][3] += c[t][3] * iB;
            }
        }

        if (h + 1 < HH) asm volatile("cp.async.wait_group 0;");
        __syncthreads();   // packed free for next convert; raw h+1 ready
    }

    // ---- epilogue: pack mean into bf16 (hi,lo) fragment words -> g_attn2 ----
    uint32_t* stg = smw;   // [112][KPAD], overlaps QP/KP (free now)
    for (int i = tid; i < QROWS * KPAD; i += K1_THREADS) stg[i] = 0u;
    __syncthreads();
#pragma unroll
    for (int t = 0; t < 13; t++) {
        if (t < cnt) {
            const int col0 = (nt0 + t) * 8 + 2 * lane4;
            const int kcg = col0 >> 4, rem = col0 & 15;
            const int wp = kcg * 16 + ((rem >> 1) & 3) * 4 + (rem >> 3);
            {
                uint32_t hw = packhi(macc[t][0], macc[t][1]);
                float l0 = macc[t][0] - trunc16(macc[t][0]);
                float l1 = macc[t][1] - trunc16(macc[t][1]);
                stg[rA * KPAD + wp] = hw;
                stg[rA * KPAD + wp + 2] = packhi(l0, l1);
            }
            {
                uint32_t hw = packhi(macc[t][2], macc[t][3]);
                float l0 = macc[t][2] - trunc16(macc[t][2]);
                float l1 = macc[t][3] - trunc16(macc[t][3]);
                stg[rB * KPAD + wp] = hw;
                stg[rB * KPAD + wp + 2] = packhi(l0, l1);
            }
        }
    }
    __syncthreads();
    for (int i = tid; i < QROWS * 56; i += K1_THREADS) {
        int row = i / 56, s4 = i % 56;
        int qg = q0 + row;
        if (qg < LK) {
            uint4 v = *((const uint4*)(stg + row * KPAD) + s4);
            *((uint4*)(g_attn2 + ((size_t)(hf * LK + qg) * NPAIR + p) * KPAD) + s4) = v;
        }
    }
}

// ===========================================================================
// Kernel 2: out = attn @ Wgather, bf16 2-term split, m16n8k16  (R5, proven)
// grid (6 c-tiles of 128, 196 q), 256 threads = 8 warps (2 mg x 4 ng)
// ===========================================================================
#define K2_THREADS 256
#define AW 6144
#define A_OFF 0
#define W_OFF (2 * AW)
#define IDXW (4 * AW)
#define SMEM2_BYTES ((IDXW + KPAD) * 4)

__device__ __forceinline__ void k2_load(
    int q, int c0, int tid, uint32_t smem_u32,
    const float* __restrict__ w1, const float* __restrict__ w2,
    const int* __restrict__ idxrow, int s)
{
    const int half = s / 7;
    const int kb = (s % 7) * 32;
    const int buf = s & 1;
#pragma unroll
    for (int t = 0; t < 4; t++) {
        int id = tid + t * K2_THREADS;
        int row = id >> 3, seg = id & 7;
        int nn = row >> 3, tt = row & 7;
        const void* src;
        if (half == 0) {
            src = (tt >= 1) ? (const void*)(g_attn2 +
                    ((size_t)q * NPAIR + nn * 7 + tt - 1) * KPAD + kb + seg * 4)
                            : (const void*)((const char*)g_zero4 + seg * 16);
        } else {
            src = (tt <= 6) ? (const void*)(g_attn2 +
                    ((size_t)(LK + q) * NPAIR + nn * 7 + tt) * KPAD + kb + seg * 4)
                            : (const void*)((const char*)g_zero4 + seg * 16);
        }
        cp16(smem_u32 + (uint32_t)(A_OFF + buf * AW + row * 48 + seg * 4) * 4, src);
    }
    const float* wb = half ? w2 : w1;
#pragma unroll
    for (int t = 0; t < 4; t++) {
        int id = tid + t * K2_THREADS;
        int kr = id >> 5, seg = id & 31;
        int r = idxrow[kb + kr];
        cp16(smem_u32 + (uint32_t)(W_OFF + buf * AW + kr * 128 + seg * 4) * 4,
             wb + (size_t)r * CDIM + c0 + seg * 4);
    }
    asm volatile("cp.async.commit_group;");
}

__global__ void __launch_bounds__(K2_THREADS, 2) out_tc_kernel(
    const float* __restrict__ w1, const float* __restrict__ w2,
    const int* __restrict__ idx, float* __restrict__ out)
{
    extern __shared__ uint32_t smw2[];
    int* idxrow = (int*)(smw2 + IDXW);
    const int q = blockIdx.y;
    const int c0 = blockIdx.x * 128;
    const int tid = threadIdx.x;
    const int lane = tid & 31;
    const int wid = tid >> 5;
    const int mg = wid >> 2, ng = wid & 3;
    const int laneq = lane >> 2, lane4 = lane & 3;

    uint32_t smem_u32;
    asm("{ .reg .u64 t; cvta.to.shared.u64 t, %1; cvt.u32.u64 %0, t; }"
        : "=r"(smem_u32) : "l"(smw2));

    for (int i = tid; i < KPAD; i += K2_THREADS)
        idxrow[i] = (i < LK) ? idx[q * LK + i] : 0;
    __syncthreads();

    float acc[4][4][4];
#pragma unroll
    for (int a = 0; a < 4; a++)
#pragma unroll
        for (int b = 0; b < 4; b++)
#pragma unroll
            for (int d = 0; d < 4; d++) acc[a][b][d] = 0.f;

    k2_load(q, c0, tid, smem_u32, w1, w2, idxrow, 0);

    for (int s = 0; s < 14; s++) {
        const int buf = s & 1;
        if (s + 1 < 14) {
            k2_load(q, c0, tid, smem_u32, w1, w2, idxrow, s + 1);
            asm volatile("cp.async.wait_group 1;");
        } else {
            asm volatile("cp.async.wait_group 0;");
        }
        __syncthreads();

        float f[4][4];
        int cc[4], ckc[4], cj[4];
#pragma unroll
        for (int t = 0; t < 4; t++) {
            int id = tid + t * K2_THREADS;
            cc[t] = id & 127;
            int kcj = id >> 7;
            ckc[t] = kcj >> 2; cj[t] = kcj & 3;
            int k0 = ckc[t] * 16 + 2 * cj[t];
            const float* wr = (const float*)(smw2 + W_OFF + buf * AW);
            f[t][0] = wr[k0 * 128 + cc[t]];
            f[t][1] = wr[(k0 + 1) * 128 + cc[t]];
            f[t][2] = wr[(k0 + 8) * 128 + cc[t]];
            f[t][3] = wr[(k0 + 9) * 128 + cc[t]];
        }
        __syncthreads();
#pragma unroll
        for (int t = 0; t < 4; t++) {
            uint4 v;
            v.x = packhi(f[t][0], f[t][1]);
            v.y = packhi(f[t][2], f[t][3]);
            float r0 = f[t][0] - trunc16(f[t][0]);
            float r1 = f[t][1] - trunc16(f[t][1]);
            float r2 = f[t][2] - trunc16(f[t][2]);
            float r3 = f[t][3] - trunc16(f[t][3]);
            v.z = packhi(r0, r1);
            v.w = packhi(r2, r3);
            *(uint4*)(smw2 + W_OFF + buf * AW + cc[t] * 48 + ckc[t] * 16 + cj[t] * 4) = v;
        }
        __syncthreads();

        const uint32_t* Ab = smw2 + A_OFF + buf * AW + (mg * 64 + laneq) * 48 + lane4 * 4;
        const uint32_t* Bb = smw2 + W_OFF + buf * AW + (ng * 32 + laneq) * 48 + lane4 * 4;
#pragma unroll
        for (int kc = 0; kc < 2; kc++) {
            uint4 bw[4];
#pragma unroll
            for (int nt = 0; nt < 4; nt++)
                bw[nt] = *(const uint4*)(Bb + nt * 8 * 48 + kc * 16);
#pragma unroll
            for (int mt = 0; mt < 4; mt++) {
                uint4 a0 = *(const uint4*)(Ab + mt * 16 * 48 + kc * 16);
                uint4 a1 = *(const uint4*)(Ab + (mt * 16 + 8) * 48 + kc * 16);
#pragma unroll
                for (int nt = 0; nt < 4; nt++) {
                    mma_bf16(acc[mt][nt], a0.x, a1.x, a0.y, a1.y, bw[nt].x, bw[nt].y);
                    mma_bf16(acc[mt][nt], a0.z, a1.z, a0.w, a1.w, bw[nt].x, bw[nt].y);
                    mma_bf16(acc[mt][nt], a0.x, a1.x, a0.y, a1.y, bw[nt].z, bw[nt].w);
                }
            }
        }
        __syncthreads();
    }

#pragma unroll
    for (int mt = 0; mt < 4; mt++) {
#pragma unroll
        for (int nt = 0; nt < 4; nt++) {
            int mrow = mg * 64 + mt * 16 + laneq;
            int col = c0 + ng * 32 + nt * 8 + 2 * lane4;
            float* ob0 = out + ((size_t)mrow * LL + q + 1) * CDIM + col;
            float* ob1 = out + ((size_t)(mrow + 8) * LL + q + 1) * CDIM + col;
            *(float2*)ob0 = make_float2(acc[mt][nt][0], acc[mt][nt][1]);
            *(float2*)ob1 = make_float2(acc[mt][nt][2], acc[mt][nt][3]);
        }
    }
}

__global__ void zero_l0_kernel(float* __restrict__ out) {
    int i = blockIdx.x * blockDim.x + threadIdx.x;   // 128*768
    int nt = i / CDIM, cc = i - nt * CDIM;
    out[(size_t)nt * LL * CDIM + cc] = 0.f;
}

extern "C" void kernel_launch(void* const* d_in, const int* in_sizes, int n_in,
                              void* d_out, int out_size)
{
    const float* q  = (const float*)d_in[0];
    const float* k  = (const float*)d_in[1];
    const float* w1 = (const float*)d_in[2];
    const float* w2 = (const float*)d_in[3];
    const int*  idx = (const int*)d_in[4];
    float* out = (float*)d_out;

    cudaFuncSetAttribute(attn_tc_kernel, cudaFuncAttributeMaxDynamicSharedMemorySize, SMEM1_BYTES);
    cudaFuncSetAttribute(out_tc_kernel, cudaFuncAttributeMaxDynamicSharedMemorySize, SMEM2_BYTES);

    attn_tc_kernel<<<dim3(2, NPAIR, 2), K1_THREADS, SMEM1_BYTES>>>(q, k);
    zero_l0_kernel<<<96, 1024>>>(out);
    out_tc_kernel<<<dim3(6, LK), K2_THREADS, SMEM2_BYTES>>>(w1, w2, idx, out);
}

// round 9
// speedup vs baseline: 2.1305x; 1.0404x over previous
#include <cuda_runtime.h>
#include <cstdint>

#define TT    8
#define LL    197
#define HH    12
#define DD    64
#define LK    196
#define NPAIR 112
#define CDIM  768
#define KPAD  224

// attn scratch, packed bf16 (hi,lo) fragment words: [half][q 196][pair 112][224 words]
__device__ uint32_t g_attn2[2u * LK * NPAIR * KPAD];
// zero source for cp.async of invalid rows
__device__ ulonglong2 g_zero4[16];

__device__ __forceinline__ void cp16(uint32_t dst, const void* src) {
    asm volatile("cp.async.cg.shared.global [%0], [%1], 16;" :: "r"(dst), "l"(src));
}
__device__ __forceinline__ float trunc16(float x) {
    return __uint_as_float(__float_as_uint(x) & 0xffff0000u);
}
__device__ __forceinline__ uint32_t packhi(float a, float b) {
    return __byte_perm(__float_as_uint(a), __float_as_uint(b), 0x7632);
}
__device__ __forceinline__ void mma_bf16(float* c,
    uint32_t a0, uint32_t a1, uint32_t a2, uint32_t a3, uint32_t b0, uint32_t b1)
{
    asm volatile("mma.sync.aligned.m16n8k16.row.col.f32.bf16.bf16.f32 "
        "{%0,%1,%2,%3},{%4,%5,%6,%7},{%8,%9},{%0,%1,%2,%3};"
        : "+f"(c[0]), "+f"(c[1]), "+f"(c[2]), "+f"(c[3])
        : "r"(a0), "r"(a1), "r"(a2), "r"(a3), "r"(b0), "r"(b1));
}
__device__ __forceinline__ void bar_pair(int id) {
    asm volatile("bar.sync %0, 64;" :: "r"(id) : "memory");
}

// ===========================================================================
// Kernel 1: bf16 2-term split tensor-core scores + softmax(no-max) + head-mean
// grid (2 qtiles, 112 pairs, 2 halves), 448 threads = 14 warps
// warp = (stripe 0..6 [m16], nhalf 0..1 [13 or 12 n-tiles of 8])
// ===========================================================================
#define K1_THREADS 448
#define QROWS 112
#define KROWS 200
#define PW    80
#define QP_OFF 0
#define KP_OFF (QROWS * PW)             // 8960
#define QR_OFF (KP_OFF + KROWS * PW)    // 24960
#define KR_OFF (QR_OFF + QROWS * 64)    // 32128
#define RED_OFF (KR_OFF + KROWS * 64)   // 44928
#define SMEM1_WORDS (RED_OFF + 224)     // 45152
#define SMEM1_BYTES (SMEM1_WORDS * 4)   // 180608

__device__ __forceinline__ void k1_load_raw(
    const float* __restrict__ q, const float* __restrict__ k,
    size_t qbase, size_t kbase, int q0, int tid, uint32_t smem_u32, int h)
{
#pragma unroll
    for (int it = 0; it < 4; it++) {
        int i = tid + it * K1_THREADS;
        int row = i >> 4, c4 = i & 15;
        int qg = q0 + row; if (qg > 195) qg = 195;
        const float* src = q + qbase + (size_t)qg * (HH * DD) + h * DD + c4 * 4;
        cp16(smem_u32 + (uint32_t)(QR_OFF + row * 64 + c4 * 4) * 4, src);
    }
#pragma unroll
    for (int it = 0; it < 8; it++) {
        int i = tid + it * K1_THREADS;
        if (i < KROWS * 16) {
            int row = i >> 4, c4 = i & 15;
            int kg = row > 195 ? 195 : row;
            const float* src = k + kbase + (size_t)kg * (HH * DD) + h * DD + c4 * 4;
            cp16(smem_u32 + (uint32_t)(KR_OFF + row * 64 + c4 * 4) * 4, src);
        }
    }
    asm volatile("cp.async.commit_group;");
}

__global__ void __launch_bounds__(K1_THREADS, 1) attn_tc_kernel(
    const float* __restrict__ q, const float* __restrict__ k)
{
    extern __shared__ float sm[];
    uint32_t* smw = (uint32_t*)sm;
    const int tid = threadIdx.x;
    const int lane = tid & 31;
    const int wid = tid >> 5;
    const int stripe = wid >> 1;
    const int nhalf = wid & 1;
    const int laneq = lane >> 2, lane4 = lane & 3;
    const int qt = blockIdx.x;
    const int p = blockIdx.y;
    const int hf = blockIdx.z;
    const int n = p / 7, tp = p % 7;
    const int tq = (hf == 0) ? tp + 1 : tp;
    const int tk = (hf == 0) ? tp : tp + 1;
    const size_t qbase = ((size_t)(n * TT + tq) * LL + 1) * (HH * DD);
    const size_t kbase = ((size_t)(n * TT + tk) * LL + 1) * (HH * DD);
    const int q0 = qt * QROWS;

    uint32_t smem_u32;
    asm("{ .reg .u64 t; cvta.to.shared.u64 t, %1; cvt.u32.u64 %0, t; }"
        : "=r"(smem_u32) : "l"(sm));

    const int nt0 = nhalf ? 13 : 0;
    const int cnt = nhalf ? 12 : 13;
    const int rA = stripe * 16 + laneq;
    const int rB = rA + 8;

    // hoisted convert-thread geometry (448 = 28*16 -> sub constant per thread)
    const int cvt_r0  = tid >> 4;          // base row, advances by 28
    const int cvt_sub = tid & 15;
    const int cvt_kcg = cvt_sub >> 2;
    const int cvt_l4  = cvt_sub & 3;
    const int cvt_src = cvt_kcg * 16 + 2 * cvt_l4;     // raw col offset
    const int cvt_dst = cvt_kcg * 16 + cvt_l4 * 4;     // packed word offset

    float macc[13][4];
#pragma unroll
    for (int t = 0; t < 13; t++)
#pragma unroll
        for (int j = 0; j < 4; j++) macc[t][j] = 0.f;

    k1_load_raw(q, k, qbase, kbase, q0, tid, smem_u32, 0);
    asm volatile("cp.async.wait_group 0;");
    __syncthreads();

    for (int h = 0; h < HH; h++) {
        // ---- convert raw fp32 -> packed bf16 (hi,lo) fragment words ----
        {
            const float* srcQ = sm + QR_OFF + cvt_r0 * 64 + cvt_src;
            uint32_t* dstQ = smw + QP_OFF + cvt_r0 * PW + cvt_dst;
#pragma unroll
            for (int it = 0; it < 4; it++) {
                float2 pA = *(const float2*)(srcQ);
                float2 pB = *(const float2*)(srcQ + 8);
                uint4 v;
                v.x = packhi(pA.x, pA.y);
                v.y = packhi(pB.x, pB.y);
                v.z = packhi(pA.x - trunc16(pA.x), pA.y - trunc16(pA.y));
                v.w = packhi(pB.x - trunc16(pB.x), pB.y - trunc16(pB.y));
                *(uint4*)(dstQ) = v;
                srcQ += 28 * 64;
                dstQ += 28 * PW;
            }
            const float* srcK = sm + KR_OFF + cvt_r0 * 64 + cvt_src;
            uint32_t* dstK = smw + KP_OFF + cvt_r0 * PW + cvt_dst;
#pragma unroll
            for (int it = 0; it < 8; it++) {
                if (cvt_r0 + it * 28 < KROWS) {
                    float2 pA = *(const float2*)(srcK);
                    float2 pB = *(const float2*)(srcK + 8);
                    uint4 v;
                    v.x = packhi(pA.x, pA.y);
                    v.y = packhi(pB.x, pB.y);
                    v.z = packhi(pA.x - trunc16(pA.x), pA.y - trunc16(pA.y));
                    v.w = packhi(pB.x - trunc16(pB.x), pB.y - trunc16(pB.y));
                    *(uint4*)(dstK) = v;
                }
                srcK += 28 * 64;
                dstK += 28 * PW;
            }
        }
        __syncthreads();                       // packed ready, raw free
        if (h + 1 < HH) k1_load_raw(q, k, qbase, kbase, q0, tid, smem_u32, h + 1);

        // ---- MMA: scores for this head ----
        float c[13][4];
#pragma unroll
        for (int t = 0; t < 13; t++)
#pragma unroll
            for (int j = 0; j < 4; j++) c[t][j] = 0.f;

#pragma unroll
        for (int kcg = 0; kcg < 4; kcg++) {
            uint4 aA = *(const uint4*)(smw + QP_OFF + rA * PW + kcg * 16 + lane4 * 4);
            uint4 aB = *(const uint4*)(smw + QP_OFF + rB * PW + kcg * 16 + lane4 * 4);
#pragma unroll
            for (int t = 0; t < 13; t++) {
                if (t < cnt) {
                    const int brow = (nt0 + t) * 8 + laneq;
                    uint4 bw = *(const uint4*)(smw + KP_OFF + brow * PW + kcg * 16 + lane4 * 4);
                    mma_bf16(c[t], aA.x, aB.x, aA.y, aB.y, bw.x, bw.y);
                    mma_bf16(c[t], aA.z, aB.z, aA.w, aB.w, bw.x, bw.y);
                    mma_bf16(c[t], aA.x, aB.x, aA.y, aB.y, bw.z, bw.w);
                }
            }
        }

        // ---- softmax without max-subtraction (logits ~ N(0,1), safe) ----
        float sA = 0.f, sB = 0.f;
#pragma unroll
        for (int t = 0; t < 13; t++) {
            if (t < cnt) {
                c[t][0] = __expf(c[t][0] * 0.125f);
                c[t][1] = __expf(c[t][1] * 0.125f);
                c[t][2] = __expf(c[t][2] * 0.125f);
                c[t][3] = __expf(c[t][3] * 0.125f);
            }
        }
        // zero invalid cols 196..199 (n-tile 24: nhalf warp, local t==11)
        if (nhalf && lane4 >= 2) {
            c[11][0] = 0.f; c[11][1] = 0.f; c[11][2] = 0.f; c[11][3] = 0.f;
        }
#pragma unroll
        for (int t = 0; t < 13; t++) {
            if (t < cnt) {
                sA += c[t][0] + c[t][1];
                sB += c[t][2] + c[t][3];
            }
        }
#pragma unroll
        for (int o = 1; o <= 2; o <<= 1) {
            sA += __shfl_xor_sync(0xffffffffu, sA, o);
            sB += __shfl_xor_sync(0xffffffffu, sB, o);
        }
        if (lane4 == 0) {
            sm[RED_OFF + rA * 2 + nhalf] = sA;
            sm[RED_OFF + rB * 2 + nhalf] = sB;
        }
        bar_pair(1 + stripe);
        sA += sm[RED_OFF + rA * 2 + (1 - nhalf)];
        sB += sm[RED_OFF + rB * 2 + (1 - nhalf)];
        const float iA = 1.0f / (12.0f * sA);
        const float iB = 1.0f / (12.0f * sB);
#pragma unroll
        for (int t = 0; t < 13; t++) {
            if (t < cnt) {
                macc[t][0] += c[t][0] * iA;
                macc[t][1] += c[t][1] * iA;
                macc[t][2] += c[t][2] * iB;
                macc[t][3] += c[t][3] * iB;
            }
        }

        if (h + 1 < HH) asm volatile("cp.async.wait_group 0;");
        __syncthreads();   // packed free for next convert; raw h+1 ready
    }

    // ---- epilogue: pack mean into bf16 (hi,lo) fragment words -> g_attn2 ----
    uint32_t* stg = smw;   // [112][KPAD], overlaps QP/KP (free now)
    for (int i = tid; i < QROWS * KPAD; i += K1_THREADS) stg[i] = 0u;
    __syncthreads();
#pragma unroll
    for (int t = 0; t < 13; t++) {
        if (t < cnt) {
            const int col0 = (nt0 + t) * 8 + 2 * lane4;
            const int kcg = col0 >> 4, rem = col0 & 15;
            const int wp = kcg * 16 + ((rem >> 1) & 3) * 4 + (rem >> 3);
            {
                uint32_t hw = packhi(macc[t][0], macc[t][1]);
                float l0 = macc[t][0] - trunc16(macc[t][0]);
                float l1 = macc[t][1] - trunc16(macc[t][1]);
                stg[rA * KPAD + wp] = hw;
                stg[rA * KPAD + wp + 2] = packhi(l0, l1);
            }
            {
                uint32_t hw = packhi(macc[t][2], macc[t][3]);
                float l0 = macc[t][2] - trunc16(macc[t][2]);
                float l1 = macc[t][3] - trunc16(macc[t][3]);
                stg[rB * KPAD + wp] = hw;
                stg[rB * KPAD + wp + 2] = packhi(l0, l1);
            }
        }
    }
    __syncthreads();
    for (int i = tid; i < QROWS * 56; i += K1_THREADS) {
        int row = i / 56, s4 = i % 56;
        int qg = q0 + row;
        if (qg < LK) {
            uint4 v = *((const uint4*)(stg + row * KPAD) + s4);
            *((uint4*)(g_attn2 + ((size_t)(hf * LK + qg) * NPAIR + p) * KPAD) + s4) = v;
        }
    }
}

// ===========================================================================
// Kernel 2: out = attn @ Wgather, bf16 2-term split, m16n8k16  (R6, proven)
// grid (6 c-tiles of 128, 196 q), 256 threads = 8 warps (2 mg x 4 ng)
// ===========================================================================
#define K2_THREADS 256
#define AW 6144
#define A_OFF 0
#define W_OFF (2 * AW)
#define IDXW (4 * AW)
#define SMEM2_BYTES ((IDXW + KPAD) * 4)

__device__ __forceinline__ void k2_load(
    int q, int c0, int tid, uint32_t smem_u32,
    const float* __restrict__ w1, const float* __restrict__ w2,
    const int* __restrict__ idxrow, int s)
{
    const int half = s / 7;
    const int kb = (s % 7) * 32;
    const int buf = s & 1;
#pragma unroll
    for (int t = 0; t < 4; t++) {
        int id = tid + t * K2_THREADS;
        int row = id >> 3, seg = id & 7;
        int nn = row >> 3, tt = row & 7;
        const void* src;
        if (half == 0) {
            src = (tt >= 1) ? (const void*)(g_attn2 +
                    ((size_t)q * NPAIR + nn * 7 + tt - 1) * KPAD + kb + seg * 4)
                            : (const void*)((const char*)g_zero4 + seg * 16);
        } else {
            src = (tt <= 6) ? (const void*)(g_attn2 +
                    ((size_t)(LK + q) * NPAIR + nn * 7 + tt) * KPAD + kb + seg * 4)
                            : (const void*)((const char*)g_zero4 + seg * 16);
        }
        cp16(smem_u32 + (uint32_t)(A_OFF + buf * AW + row * 48 + seg * 4) * 4, src);
    }
    const float* wb = half ? w2 : w1;
#pragma unroll
    for (int t = 0; t < 4; t++) {
        int id = tid + t * K2_THREADS;
        int kr = id >> 5, seg = id & 31;
        int r = idxrow[kb + kr];
        cp16(smem_u32 + (uint32_t)(W_OFF + buf * AW + kr * 128 + seg * 4) * 4,
             wb + (size_t)r * CDIM + c0 + seg * 4);
    }
    asm volatile("cp.async.commit_group;");
}

__global__ void __launch_bounds__(K2_THREADS, 2) out_tc_kernel(
    const float* __restrict__ w1, const float* __restrict__ w2,
    const int* __restrict__ idx, float* __restrict__ out)
{
    extern __shared__ uint32_t smw2[];
    int* idxrow = (int*)(smw2 + IDXW);
    const int q = blockIdx.y;
    const int c0 = blockIdx.x * 128;
    const int tid = threadIdx.x;
    const int lane = tid & 31;
    const int wid = tid >> 5;
    const int mg = wid >> 2, ng = wid & 3;
    const int laneq = lane >> 2, lane4 = lane & 3;

    uint32_t smem_u32;
    asm("{ .reg .u64 t; cvta.to.shared.u64 t, %1; cvt.u32.u64 %0, t; }"
        : "=r"(smem_u32) : "l"(smw2));

    for (int i = tid; i < KPAD; i += K2_THREADS)
        idxrow[i] = (i < LK) ? idx[q * LK + i] : 0;
    __syncthreads();

    float acc[4][4][4];
#pragma unroll
    for (int a = 0; a < 4; a++)
#pragma unroll
        for (int b = 0; b < 4; b++)
#pragma unroll
            for (int d = 0; d < 4; d++) acc[a][b][d] = 0.f;

    k2_load(q, c0, tid, smem_u32, w1, w2, idxrow, 0);

    for (int s = 0; s < 14; s++) {
        const int buf = s & 1;
        if (s + 1 < 14) {
            k2_load(q, c0, tid, smem_u32, w1, w2, idxrow, s + 1);
            asm volatile("cp.async.wait_group 1;");
        } else {
            asm volatile("cp.async.wait_group 0;");
        }
        __syncthreads();

        float f[4][4];
        int cc[4], ckc[4], cj[4];
#pragma unroll
        for (int t = 0; t < 4; t++) {
            int id = tid + t * K2_THREADS;
            cc[t] = id & 127;
            int kcj = id >> 7;
            ckc[t] = kcj >> 2; cj[t] = kcj & 3;
            int k0 = ckc[t] * 16 + 2 * cj[t];
            const float* wr = (const float*)(smw2 + W_OFF + buf * AW);
            f[t][0] = wr[k0 * 128 + cc[t]];
            f[t][1] = wr[(k0 + 1) * 128 + cc[t]];
            f[t][2] = wr[(k0 + 8) * 128 + cc[t]];
            f[t][3] = wr[(k0 + 9) * 128 + cc[t]];
        }
        __syncthreads();
#pragma unroll
        for (int t = 0; t < 4; t++) {
            uint4 v;
            v.x = packhi(f[t][0], f[t][1]);
            v.y = packhi(f[t][2], f[t][3]);
            float r0 = f[t][0] - trunc16(f[t][0]);
            float r1 = f[t][1] - trunc16(f[t][1]);
            float r2 = f[t][2] - trunc16(f[t][2]);
            float r3 = f[t][3] - trunc16(f[t][3]);
            v.z = packhi(r0, r1);
            v.w = packhi(r2, r3);
            *(uint4*)(smw2 + W_OFF + buf * AW + cc[t] * 48 + ckc[t] * 16 + cj[t] * 4) = v;
        }
        __syncthreads();

        const uint32_t* Ab = smw2 + A_OFF + buf * AW + (mg * 64 + laneq) * 48 + lane4 * 4;
        const uint32_t* Bb = smw2 + W_OFF + buf * AW + (ng * 32 + laneq) * 48 + lane4 * 4;
#pragma unroll
        for (int kc = 0; kc < 2; kc++) {
            uint4 bw[4];
#pragma unroll
            for (int nt = 0; nt < 4; nt++)
                bw[nt] = *(const uint4*)(Bb + nt * 8 * 48 + kc * 16);
#pragma unroll
            for (int mt = 0; mt < 4; mt++) {
                uint4 a0 = *(const uint4*)(Ab + mt * 16 * 48 + kc * 16);
                uint4 a1 = *(const uint4*)(Ab + (mt * 16 + 8) * 48 + kc * 16);
#pragma unroll
                for (int nt = 0; nt < 4; nt++) {
                    mma_bf16(acc[mt][nt], a0.x, a1.x, a0.y, a1.y, bw[nt].x, bw[nt].y);
                    mma_bf16(acc[mt][nt], a0.z, a1.z, a0.w, a1.w, bw[nt].x, bw[nt].y);
                    mma_bf16(acc[mt][nt], a0.x, a1.x, a0.y, a1.y, bw[nt].z, bw[nt].w);
                }
            }
        }
        __syncthreads();
    }

#pragma unroll
    for (int mt = 0; mt < 4; mt++) {
#pragma unroll
        for (int nt = 0; nt < 4; nt++) {
            int mrow = mg * 64 + mt * 16 + laneq;
            int col = c0 + ng * 32 + nt * 8 + 2 * lane4;
            float* ob0 = out + ((size_t)mrow * LL + q + 1) * CDIM + col;
            float* ob1 = out + ((size_t)(mrow + 8) * LL + q + 1) * CDIM + col;
            *(float2*)ob0 = make_float2(acc[mt][nt][0], acc[mt][nt][1]);
            *(float2*)ob1 = make_float2(acc[mt][nt][2], acc[mt][nt][3]);
        }
    }
}

__global__ void zero_l0_kernel(float* __restrict__ out) {
    int i = blockIdx.x * blockDim.x + threadIdx.x;   // 128*768
    int nt = i / CDIM, cc = i - nt * CDIM;
    out[(size_t)nt * LL * CDIM + cc] = 0.f;
}

extern "C" void kernel_launch(void* const* d_in, const int* in_sizes, int n_in,
                              void* d_out, int out_size)
{
    const float* q  = (const float*)d_in[0];
    const float* k  = (const float*)d_in[1];
    const float* w1 = (const float*)d_in[2];
    const float* w2 = (const float*)d_in[3];
    const int*  idx = (const int*)d_in[4];
    float* out = (float*)d_out;

    cudaFuncSetAttribute(attn_tc_kernel, cudaFuncAttributeMaxDynamicSharedMemorySize, SMEM1_BYTES);
    cudaFuncSetAttribute(out_tc_kernel, cudaFuncAttributeMaxDynamicSharedMemorySize, SMEM2_BYTES);

    attn_tc_kernel<<<dim3(2, NPAIR, 2), K1_THREADS, SMEM1_BYTES>>>(q, k);
    zero_l0_kernel<<<96, 1024>>>(out);
    out_tc_kernel<<<dim3(6, LK), K2_THREADS, SMEM2_BYTES>>>(w1, w2, idx, out);
}

// round 10
// speedup vs baseline: 2.2670x; 1.0641x over previous
#include <cuda_runtime.h>
#include <cstdint>

#define TT    8
#define LL    197
#define HH    12
#define DD    64
#define LK    196
#define NPAIR 112
#define CDIM  768
#define KPAD  224

// attn scratch, packed bf16 (hi,lo) fragment words: [half][q 196][pair 112][224 words]
__device__ uint32_t g_attn2[2u * LK * NPAIR * KPAD];
// zero source for cp.async of invalid rows
__device__ ulonglong2 g_zero4[16];

__device__ __forceinline__ void cp16(uint32_t dst, const void* src) {
    asm volatile("cp.async.cg.shared.global [%0], [%1], 16;" :: "r"(dst), "l"(src));
}
__device__ __forceinline__ float trunc16(float x) {
    return __uint_as_float(__float_as_uint(x) & 0xffff0000u);
}
__device__ __forceinline__ uint32_t packhi(float a, float b) {
    return __byte_perm(__float_as_uint(a), __float_as_uint(b), 0x7632);
}
__device__ __forceinline__ uint32_t packlo(float a, float b) {
    return packhi(a - trunc16(a), b - trunc16(b));
}
__device__ __forceinline__ void mma_bf16(float* c,
    uint32_t a0, uint32_t a1, uint32_t a2, uint32_t a3, uint32_t b0, uint32_t b1)
{
    asm volatile("mma.sync.aligned.m16n8k16.row.col.f32.bf16.bf16.f32 "
        "{%0,%1,%2,%3},{%4,%5,%6,%7},{%8,%9},{%0,%1,%2,%3};"
        : "+f"(c[0]), "+f"(c[1]), "+f"(c[2]), "+f"(c[3])
        : "r"(a0), "r"(a1), "r"(a2), "r"(a3), "r"(b0), "r"(b1));
}
__device__ __forceinline__ void bar_pair(int id) {
    asm volatile("bar.sync %0, 64;" :: "r"(id) : "memory");
}

// ===========================================================================
// Kernel 1: bf16 2-term split scores + softmax(no-max) + head-mean
// grid (2 qtiles, 112 pairs, 2 halves), 448 threads = 14 warps
// warp = (stripe 0..6 [m16], nhalf 0..1 [13 or 12 n-tiles of 8])
// Q raw (pitch 88, double-buffered) -> A-frags packed in registers.
// K raw (pitch 64) -> packed KP (pitch 80) via self-consistent cp.async:
//   each thread converts exactly the bytes it copied (no barrier needed),
//   shfl.xor(2) pairs float4s into fragment words.
// ===========================================================================
#define K1_THREADS 448
#define QROWS 112
#define KROWS 200
#define QPITCH 88
#define QBUF (QROWS * QPITCH)            // 9856 words
#define QR_OFF 0
#define KR_OFF (2 * QBUF)                // 19712
#define KP_OFF (KR_OFF + KROWS * 64)     // 32512
#define RED_OFF (KP_OFF + KROWS * 80)    // 48512
#define SMEM1_WORDS (RED_OFF + 224)      // 48736
#define SMEM1_BYTES (SMEM1_WORDS * 4)    // 194944

// Q: 112 rows x 16 cp16 into buf
__device__ __forceinline__ void k1_load_q(
    const float* __restrict__ q, size_t qbase, int q0,
    int tid, uint32_t smem_u32, int h, int buf)
{
#pragma unroll
    for (int it = 0; it < 4; it++) {
        int i = tid + it * K1_THREADS;
        int row = i >> 4, c4 = i & 15;
        int qg = q0 + row; if (qg > 195) qg = 195;
        const float* src = q + qbase + (size_t)qg * (HH * DD) + h * DD + c4 * 4;
        cp16(smem_u32 + (uint32_t)(QR_OFF + buf * QBUF + row * QPITCH + c4 * 4) * 4, src);
    }
    asm volatile("cp.async.commit_group;");
}

__global__ void __launch_bounds__(K1_THREADS, 1) attn_tc_kernel(
    const float* __restrict__ q, const float* __restrict__ k)
{
    extern __shared__ float sm[];
    uint32_t* smw = (uint32_t*)sm;
    const int tid = threadIdx.x;
    const int lane = tid & 31;
    const int wid = tid >> 5;
    const int stripe = wid >> 1;
    const int nhalf = wid & 1;
    const int laneq = lane >> 2, lane4 = lane & 3;
    const int qt = blockIdx.x;
    const int p = blockIdx.y;
    const int hf = blockIdx.z;
    const int n = p / 7, tp = p % 7;
    const int tq = (hf == 0) ? tp + 1 : tp;
    const int tk = (hf == 0) ? tp : tp + 1;
    const size_t qbase = ((size_t)(n * TT + tq) * LL + 1) * (HH * DD);
    const size_t kbase = ((size_t)(n * TT + tk) * LL + 1) * (HH * DD);
    const int q0 = qt * QROWS;

    uint32_t smem_u32;
    asm("{ .reg .u64 t; cvta.to.shared.u64 t, %1; cvt.u32.u64 %0, t; }"
        : "=r"(smem_u32) : "l"(sm));

    const int nt0 = nhalf ? 13 : 0;
    const int cnt = nhalf ? 12 : 13;
    const int rA = stripe * 16 + laneq;
    const int rB = rA + 8;

    // per-thread K pipeline geometry (3200 units = 200 rows x 16 float4)
    const int ku = tid & 15;                  // float4 index within row
    const int kcg = ku >> 2, kw = ku & 3;     // fragment group / quad pos
    const int kl4out = ((kw & 1) << 1) | (kw >> 1);
    const int kr0 = tid >> 4;                 // base row (advances by 28)

    float macc[13][4];
#pragma unroll
    for (int t = 0; t < 13; t++)
#pragma unroll
        for (int j = 0; j < 4; j++) macc[t][j] = 0.f;

    // ---- prologue: issue K(0) and Q(0) ----
#pragma unroll
    for (int it = 0; it < 8; it++) {
        if (it < 7 || tid < 64) {
            int r = kr0 + it * 28;
            int kg = r > 195 ? 195 : r;
            cp16(smem_u32 + (uint32_t)(KR_OFF + r * 64 + ku * 4) * 4,
                 k + kbase + (size_t)kg * (HH * DD) + 0 * DD + ku * 4);
        }
    }
    asm volatile("cp.async.commit_group;");
    k1_load_q(q, qbase, q0, tid, smem_u32, 0, 0);

    for (int h = 0; h < HH; h++) {
        const int buf = h & 1;
        asm volatile("cp.async.wait_group 0;");   // K(h), Q(h) landed

        // ---- K convert (self-bytes, no barrier) + fused K(h+1) issue ----
#pragma unroll
        for (int it = 0; it < 8; it++) {
            if (it < 7 || tid < 64) {
                int r = kr0 + it * 28;
                float4 O = *(const float4*)(sm + KR_OFF + r * 64 + ku * 4);
                float4 P;
                P.x = __shfl_xor_sync(0xffffffffu, O.x, 2);
                P.y = __shfl_xor_sync(0xffffffffu, O.y, 2);
                P.z = __shfl_xor_sync(0xffffffffu, O.z, 2);
                P.w = __shfl_xor_sync(0xffffffffu, O.w, 2);
                float f0, f1, f2, f3;
                if (kw & 2) { f0 = P.z; f1 = P.w; f2 = O.z; f3 = O.w; }
                else        { f0 = O.x; f1 = O.y; f2 = P.x; f3 = P.y; }
                uint4 v;
                v.x = packhi(f0, f1);
                v.y = packhi(f2, f3);
                v.z = packlo(f0, f1);
                v.w = packlo(f2, f3);
                *(uint4*)(smw + KP_OFF + r * 80 + kcg * 16 + kl4out * 4) = v;
                if (h + 1 < HH) {
                    int kg = r > 195 ? 195 : r;
                    cp16(smem_u32 + (uint32_t)(KR_OFF + r * 64 + ku * 4) * 4,
                         k + kbase + (size_t)kg * (HH * DD) + (h + 1) * DD + ku * 4);
                }
            }
        }
        asm volatile("cp.async.commit_group;");
        if (h + 1 < HH) k1_load_q(q, qbase, q0, tid, smem_u32, h + 1, buf ^ 1);
        __syncthreads();                          // KP(h) visible to all

        // ---- MMA: A-frags packed in registers from raw Q ----
        float c[13][4];
#pragma unroll
        for (int t = 0; t < 13; t++)
#pragma unroll
            for (int j = 0; j < 4; j++) c[t][j] = 0.f;

        const float* QRb = sm + QR_OFF + buf * QBUF;
#pragma unroll
        for (int kc = 0; kc < 4; kc++) {
            const int qoff = kc * 16 + 2 * lane4;
            float2 qa0 = *(const float2*)(QRb + rA * QPITCH + qoff);
            float2 qa1 = *(const float2*)(QRb + rA * QPITCH + qoff + 8);
            float2 qb0 = *(const float2*)(QRb + rB * QPITCH + qoff);
            float2 qb1 = *(const float2*)(QRb + rB * QPITCH + qoff + 8);
            uint32_t aAx = packhi(qa0.x, qa0.y), aAy = packhi(qa1.x, qa1.y);
            uint32_t aAz = packlo(qa0.x, qa0.y), aAw = packlo(qa1.x, qa1.y);
            uint32_t aBx = packhi(qb0.x, qb0.y), aBy = packhi(qb1.x, qb1.y);
            uint32_t aBz = packlo(qb0.x, qb0.y), aBw = packlo(qb1.x, qb1.y);
#pragma unroll
            for (int t = 0; t < 13; t++) {
                if (t < cnt) {
                    const int brow = (nt0 + t) * 8 + laneq;
                    uint4 bw = *(const uint4*)(smw + KP_OFF + brow * 80 + kc * 16 + lane4 * 4);
                    mma_bf16(c[t], aAx, aBx, aAy, aBy, bw.x, bw.y);
                    mma_bf16(c[t], aAz, aBz, aAw, aBw, bw.x, bw.y);
                    mma_bf16(c[t], aAx, aBx, aAy, aBy, bw.z, bw.w);
                }
            }
        }

        // ---- softmax without max-subtraction ----
        float sA = 0.f, sB = 0.f;
#pragma unroll
        for (int t = 0; t < 13; t++) {
            if (t < cnt) {
                c[t][0] = __expf(c[t][0] * 0.125f);
                c[t][1] = __expf(c[t][1] * 0.125f);
                c[t][2] = __expf(c[t][2] * 0.125f);
                c[t][3] = __expf(c[t][3] * 0.125f);
            }
        }
        if (nhalf && lane4 >= 2) {
            c[11][0] = 0.f; c[11][1] = 0.f; c[11][2] = 0.f; c[11][3] = 0.f;
        }
#pragma unroll
        for (int t = 0; t < 13; t++) {
            if (t < cnt) {
                sA += c[t][0] + c[t][1];
                sB += c[t][2] + c[t][3];
            }
        }
#pragma unroll
        for (int o = 1; o <= 2; o <<= 1) {
            sA += __shfl_xor_sync(0xffffffffu, sA, o);
            sB += __shfl_xor_sync(0xffffffffu, sB, o);
        }
        if (lane4 == 0) {
            sm[RED_OFF + rA * 2 + nhalf] = sA;
            sm[RED_OFF + rB * 2 + nhalf] = sB;
        }
        bar_pair(1 + stripe);
        sA += sm[RED_OFF + rA * 2 + (1 - nhalf)];
        sB += sm[RED_OFF + rB * 2 + (1 - nhalf)];
        const float iA = 1.0f / (12.0f * sA);
        const float iB = 1.0f / (12.0f * sB);
#pragma unroll
        for (int t = 0; t < 13; t++) {
            if (t < cnt) {
                macc[t][0] += c[t][0] * iA;
                macc[t][1] += c[t][1] * iA;
                macc[t][2] += c[t][2] * iB;
                macc[t][3] += c[t][3] * iB;
            }
        }
        __syncthreads();    // QR(buf)/KP free for next head's convert & loads
    }

    // ---- epilogue: pack mean into bf16 (hi,lo) fragment words -> g_attn2 ----
    uint32_t* stg = smw;   // [112][KPAD], overlaps QR/KR (free now)
    for (int i = tid; i < QROWS * KPAD; i += K1_THREADS) stg[i] = 0u;
    __syncthreads();
#pragma unroll
    for (int t = 0; t < 13; t++) {
        if (t < cnt) {
            const int col0 = (nt0 + t) * 8 + 2 * lane4;
            const int kcg2 = col0 >> 4, rem = col0 & 15;
            const int wp = kcg2 * 16 + ((rem >> 1) & 3) * 4 + (rem >> 3);
            stg[rA * KPAD + wp]     = packhi(macc[t][0], macc[t][1]);
            stg[rA * KPAD + wp + 2] = packlo(macc[t][0], macc[t][1]);
            stg[rB * KPAD + wp]     = packhi(macc[t][2], macc[t][3]);
            stg[rB * KPAD + wp + 2] = packlo(macc[t][2], macc[t][3]);
        }
    }
    __syncthreads();
    for (int i = tid; i < QROWS * 56; i += K1_THREADS) {
        int row = i / 56, s4 = i % 56;
        int qg = q0 + row;
        if (qg < LK) {
            uint4 v = *((const uint4*)(stg + row * KPAD) + s4);
            *((uint4*)(g_attn2 + ((size_t)(hf * LK + qg) * NPAIR + p) * KPAD) + s4) = v;
        }
    }
}

// ===========================================================================
// Kernel 2: out = attn @ Wgather, bf16 2-term split, m16n8k16  (proven)
// grid (6 c-tiles of 128, 196 q), 256 threads = 8 warps (2 mg x 4 ng)
// ===========================================================================
#define K2_THREADS 256
#define AW 6144
#define A_OFF 0
#define W_OFF (2 * AW)
#define IDXW (4 * AW)
#define SMEM2_BYTES ((IDXW + KPAD) * 4)

__device__ __forceinline__ void k2_load(
    int q, int c0, int tid, uint32_t smem_u32,
    const float* __restrict__ w1, const float* __restrict__ w2,
    const int* __restrict__ idxrow, int s)
{
    const int half = s / 7;
    const int kb = (s % 7) * 32;
    const int buf = s & 1;
#pragma unroll
    for (int t = 0; t < 4; t++) {
        int id = tid + t * K2_THREADS;
        int row = id >> 3, seg = id & 7;
        int nn = row >> 3, tt = row & 7;
        const void* src;
        if (half == 0) {
            src = (tt >= 1) ? (const void*)(g_attn2 +
                    ((size_t)q * NPAIR + nn * 7 + tt - 1) * KPAD + kb + seg * 4)
                            : (const void*)((const char*)g_zero4 + seg * 16);
        } else {
            src = (tt <= 6) ? (const void*)(g_attn2 +
                    ((size_t)(LK + q) * NPAIR + nn * 7 + tt) * KPAD + kb + seg * 4)
                            : (const void*)((const char*)g_zero4 + seg * 16);
        }
        cp16(smem_u32 + (uint32_t)(A_OFF + buf * AW + row * 48 + seg * 4) * 4, src);
    }
    const float* wb = half ? w2 : w1;
#pragma unroll
    for (int t = 0; t < 4; t++) {
        int id = tid + t * K2_THREADS;
        int kr = id >> 5, seg = id & 31;
        int r = idxrow[kb + kr];
        cp16(smem_u32 + (uint32_t)(W_OFF + buf * AW + kr * 128 + seg * 4) * 4,
             wb + (size_t)r * CDIM + c0 + seg * 4);
    }
    asm volatile("cp.async.commit_group;");
}

__global__ void __launch_bounds__(K2_THREADS, 2) out_tc_kernel(
    const float* __restrict__ w1, const float* __restrict__ w2,
    const int* __restrict__ idx, float* __restrict__ out)
{
    extern __shared__ uint32_t smw2[];
    int* idxrow = (int*)(smw2 + IDXW);
    const int q = blockIdx.y;
    const int c0 = blockIdx.x * 128;
    const int tid = threadIdx.x;
    const int lane = tid & 31;
    const int wid = tid >> 5;
    const int mg = wid >> 2, ng = wid & 3;
    const int laneq = lane >> 2, lane4 = lane & 3;

    uint32_t smem_u32;
    asm("{ .reg .u64 t; cvta.to.shared.u64 t, %1; cvt.u32.u64 %0, t; }"
        : "=r"(smem_u32) : "l"(smw2));

    for (int i = tid; i < KPAD; i += K2_THREADS)
        idxrow[i] = (i < LK) ? idx[q * LK + i] : 0;
    __syncthreads();

    float acc[4][4][4];
#pragma unroll
    for (int a = 0; a < 4; a++)
#pragma unroll
        for (int b = 0; b < 4; b++)
#pragma unroll
            for (int d = 0; d < 4; d++) acc[a][b][d] = 0.f;

    k2_load(q, c0, tid, smem_u32, w1, w2, idxrow, 0);

    for (int s = 0; s < 14; s++) {
        const int buf = s & 1;
        if (s + 1 < 14) {
            k2_load(q, c0, tid, smem_u32, w1, w2, idxrow, s + 1);
            asm volatile("cp.async.wait_group 1;");
        } else {
            asm volatile("cp.async.wait_group 0;");
        }
        __syncthreads();

        float f[4][4];
        int cc[4], ckc[4], cj[4];
#pragma unroll
        for (int t = 0; t < 4; t++) {
            int id = tid + t * K2_THREADS;
            cc[t] = id & 127;
            int kcj = id >> 7;
            ckc[t] = kcj >> 2; cj[t] = kcj & 3;
            int k0 = ckc[t] * 16 + 2 * cj[t];
            const float* wr = (const float*)(smw2 + W_OFF + buf * AW);
            f[t][0] = wr[k0 * 128 + cc[t]];
            f[t][1] = wr[(k0 + 1) * 128 + cc[t]];
            f[t][2] = wr[(k0 + 8) * 128 + cc[t]];
            f[t][3] = wr[(k0 + 9) * 128 + cc[t]];
        }
        __syncthreads();
#pragma unroll
        for (int t = 0; t < 4; t++) {
            uint4 v;
            v.x = packhi(f[t][0], f[t][1]);
            v.y = packhi(f[t][2], f[t][3]);
            v.z = packlo(f[t][0], f[t][1]);
            v.w = packlo(f[t][2], f[t][3]);
            *(uint4*)(smw2 + W_OFF + buf * AW + cc[t] * 48 + ckc[t] * 16 + cj[t] * 4) = v;
        }
        __syncthreads();

        const uint32_t* Ab = smw2 + A_OFF + buf * AW + (mg * 64 + laneq) * 48 + lane4 * 4;
        const uint32_t* Bb = smw2 + W_OFF + buf * AW + (ng * 32 + laneq) * 48 + lane4 * 4;
#pragma unroll
        for (int kc = 0; kc < 2; kc++) {
            uint4 bw[4];
#pragma unroll
            for (int nt = 0; nt < 4; nt++)
                bw[nt] = *(const uint4*)(Bb + nt * 8 * 48 + kc * 16);
#pragma unroll
            for (int mt = 0; mt < 4; mt++) {
                uint4 a0 = *(const uint4*)(Ab + mt * 16 * 48 + kc * 16);
                uint4 a1 = *(const uint4*)(Ab + (mt * 16 + 8) * 48 + kc * 16);
#pragma unroll
                for (int nt = 0; nt < 4; nt++) {
                    mma_bf16(acc[mt][nt], a0.x, a1.x, a0.y, a1.y, bw[nt].x, bw[nt].y);
                    mma_bf16(acc[mt][nt], a0.z, a1.z, a0.w, a1.w, bw[nt].x, bw[nt].y);
                    mma_bf16(acc[mt][nt], a0.x, a1.x, a0.y, a1.y, bw[nt].z, bw[nt].w);
                }
            }
        }
        __syncthreads();
    }

#pragma unroll
    for (int mt = 0; mt < 4; mt++) {
#pragma unroll
        for (int nt = 0; nt < 4; nt++) {
            int mrow = mg * 64 + mt * 16 + laneq;
            int col = c0 + ng * 32 + nt * 8 + 2 * lane4;
            float* ob0 = out + ((size_t)mrow * LL + q + 1) * CDIM + col;
            float* ob1 = out + ((size_t)(mrow + 8) * LL + q + 1) * CDIM + col;
            *(float2*)ob0 = make_float2(acc[mt][nt][0], acc[mt][nt][1]);
            *(float2*)ob1 = make_float2(acc[mt][nt][2], acc[mt][nt][3]);
        }
    }
}

__global__ void zero_l0_kernel(float* __restrict__ out) {
    int i = blockIdx.x * blockDim.x + threadIdx.x;   // 128*768
    int nt = i / CDIM, cc = i - nt * CDIM;
    out[(size_t)nt * LL * CDIM + cc] = 0.f;
}

extern "C" void kernel_launch(void* const* d_in, const int* in_sizes, int n_in,
                              void* d_out, int out_size)
{
    const float* q  = (const float*)d_in[0];
    const float* k  = (const float*)d_in[1];
    const float* w1 = (const float*)d_in[2];
    const float* w2 = (const float*)d_in[3];
    const int*  idx = (const int*)d_in[4];
    float* out = (float*)d_out;

    cudaFuncSetAttribute(attn_tc_kernel, cudaFuncAttributeMaxDynamicSharedMemorySize, SMEM1_BYTES);
    cudaFuncSetAttribute(out_tc_kernel, cudaFuncAttributeMaxDynamicSharedMemorySize, SMEM2_BYTES);

    attn_tc_kernel<<<dim3(2, NPAIR, 2), K1_THREADS, SMEM1_BYTES>>>(q, k);
    zero_l0_kernel<<<96, 1024>>>(out);
    out_tc_kernel<<<dim3(6, LK), K2_THREADS, SMEM2_BYTES>>>(w1, w2, idx, out);
}

// round 11
// speedup vs baseline: 2.2723x; 1.0023x over previous
#include <cuda_runtime.h>
#include <cstdint>

#define TT    8
#define LL    197
#define HH    12
#define DD    64
#define LK    196
#define NPAIR 112
#define CDIM  768
#define KPAD  224

// attn scratch, packed bf16 (hi,lo) fragment words: [half][q 196][pair 112][224 words]
__device__ uint32_t g_attn2[2u * LK * NPAIR * KPAD];
// zero source for cp.async of invalid rows
__device__ ulonglong2 g_zero4[16];

__device__ __forceinline__ void cp16(uint32_t dst, const void* src) {
    asm volatile("cp.async.cg.shared.global [%0], [%1], 16;" :: "r"(dst), "l"(src));
}
__device__ __forceinline__ float trunc16(float x) {
    return __uint_as_float(__float_as_uint(x) & 0xffff0000u);
}
__device__ __forceinline__ uint32_t packhi(float a, float b) {
    return __byte_perm(__float_as_uint(a), __float_as_uint(b), 0x7632);
}
__device__ __forceinline__ uint32_t packlo(float a, float b) {
    return packhi(a - trunc16(a), b - trunc16(b));
}
__device__ __forceinline__ void mma_bf16(float* c,
    uint32_t a0, uint32_t a1, uint32_t a2, uint32_t a3, uint32_t b0, uint32_t b1)
{
    asm volatile("mma.sync.aligned.m16n8k16.row.col.f32.bf16.bf16.f32 "
        "{%0,%1,%2,%3},{%4,%5,%6,%7},{%8,%9},{%0,%1,%2,%3};"
        : "+f"(c[0]), "+f"(c[1]), "+f"(c[2]), "+f"(c[3])
        : "r"(a0), "r"(a1), "r"(a2), "r"(a3), "r"(b0), "r"(b1));
}
__device__ __forceinline__ void bar_pair(int id) {
    asm volatile("bar.sync %0, 64;" :: "r"(id) : "memory");
}

// ===========================================================================
// Kernel 1: bf16 2-term split scores + softmax(no-max) + head-mean (R10, proven)
// grid (2 qtiles, 112 pairs, 2 halves), 448 threads = 14 warps
// ===========================================================================
#define K1_THREADS 448
#define QROWS 112
#define KROWS 200
#define QPITCH 88
#define QBUF (QROWS * QPITCH)            // 9856 words
#define QR_OFF 0
#define KR_OFF (2 * QBUF)                // 19712
#define KP_OFF (KR_OFF + KROWS * 64)     // 32512
#define RED_OFF (KP_OFF + KROWS * 80)    // 48512
#define SMEM1_WORDS (RED_OFF + 224)      // 48736
#define SMEM1_BYTES (SMEM1_WORDS * 4)    // 194944

__device__ __forceinline__ void k1_load_q(
    const float* __restrict__ q, size_t qbase, int q0,
    int tid, uint32_t smem_u32, int h, int buf)
{
#pragma unroll
    for (int it = 0; it < 4; it++) {
        int i = tid + it * K1_THREADS;
        int row = i >> 4, c4 = i & 15;
        int qg = q0 + row; if (qg > 195) qg = 195;
        const float* src = q + qbase + (size_t)qg * (HH * DD) + h * DD + c4 * 4;
        cp16(smem_u32 + (uint32_t)(QR_OFF + buf * QBUF + row * QPITCH + c4 * 4) * 4, src);
    }
    asm volatile("cp.async.commit_group;");
}

__global__ void __launch_bounds__(K1_THREADS, 1) attn_tc_kernel(
    const float* __restrict__ q, const float* __restrict__ k)
{
    extern __shared__ float sm[];
    uint32_t* smw = (uint32_t*)sm;
    const int tid = threadIdx.x;
    const int lane = tid & 31;
    const int wid = tid >> 5;
    const int stripe = wid >> 1;
    const int nhalf = wid & 1;
    const int laneq = lane >> 2, lane4 = lane & 3;
    const int qt = blockIdx.x;
    const int p = blockIdx.y;
    const int hf = blockIdx.z;
    const int n = p / 7, tp = p % 7;
    const int tq = (hf == 0) ? tp + 1 : tp;
    const int tk = (hf == 0) ? tp : tp + 1;
    const size_t qbase = ((size_t)(n * TT + tq) * LL + 1) * (HH * DD);
    const size_t kbase = ((size_t)(n * TT + tk) * LL + 1) * (HH * DD);
    const int q0 = qt * QROWS;

    uint32_t smem_u32;
    asm("{ .reg .u64 t; cvta.to.shared.u64 t, %1; cvt.u32.u64 %0, t; }"
        : "=r"(smem_u32) : "l"(sm));

    const int nt0 = nhalf ? 13 : 0;
    const int cnt = nhalf ? 12 : 13;
    const int rA = stripe * 16 + laneq;
    const int rB = rA + 8;

    const int ku = tid & 15;
    const int kcg = ku >> 2, kw = ku & 3;
    const int kl4out = ((kw & 1) << 1) | (kw >> 1);
    const int kr0 = tid >> 4;

    float macc[13][4];
#pragma unroll
    for (int t = 0; t < 13; t++)
#pragma unroll
        for (int j = 0; j < 4; j++) macc[t][j] = 0.f;

#pragma unroll
    for (int it = 0; it < 8; it++) {
        if (it < 7 || tid < 64) {
            int r = kr0 + it * 28;
            int kg = r > 195 ? 195 : r;
            cp16(smem_u32 + (uint32_t)(KR_OFF + r * 64 + ku * 4) * 4,
                 k + kbase + (size_t)kg * (HH * DD) + 0 * DD + ku * 4);
        }
    }
    asm volatile("cp.async.commit_group;");
    k1_load_q(q, qbase, q0, tid, smem_u32, 0, 0);

    for (int h = 0; h < HH; h++) {
        const int buf = h & 1;
        asm volatile("cp.async.wait_group 0;");

#pragma unroll
        for (int it = 0; it < 8; it++) {
            if (it < 7 || tid < 64) {
                int r = kr0 + it * 28;
                float4 O = *(const float4*)(sm + KR_OFF + r * 64 + ku * 4);
                float4 P;
                P.x = __shfl_xor_sync(0xffffffffu, O.x, 2);
                P.y = __shfl_xor_sync(0xffffffffu, O.y, 2);
                P.z = __shfl_xor_sync(0xffffffffu, O.z, 2);
                P.w = __shfl_xor_sync(0xffffffffu, O.w, 2);
                float f0, f1, f2, f3;
                if (kw & 2) { f0 = P.z; f1 = P.w; f2 = O.z; f3 = O.w; }
                else        { f0 = O.x; f1 = O.y; f2 = P.x; f3 = P.y; }
                uint4 v;
                v.x = packhi(f0, f1);
                v.y = packhi(f2, f3);
                v.z = packlo(f0, f1);
                v.w = packlo(f2, f3);
                *(uint4*)(smw + KP_OFF + r * 80 + kcg * 16 + kl4out * 4) = v;
                if (h + 1 < HH) {
                    int kg = r > 195 ? 195 : r;
                    cp16(smem_u32 + (uint32_t)(KR_OFF + r * 64 + ku * 4) * 4,
                         k + kbase + (size_t)kg * (HH * DD) + (h + 1) * DD + ku * 4);
                }
            }
        }
        asm volatile("cp.async.commit_group;");
        if (h + 1 < HH) k1_load_q(q, qbase, q0, tid, smem_u32, h + 1, buf ^ 1);
        __syncthreads();

        float c[13][4];
#pragma unroll
        for (int t = 0; t < 13; t++)
#pragma unroll
            for (int j = 0; j < 4; j++) c[t][j] = 0.f;

        const float* QRb = sm + QR_OFF + buf * QBUF;
#pragma unroll
        for (int kc = 0; kc < 4; kc++) {
            const int qoff = kc * 16 + 2 * lane4;
            float2 qa0 = *(const float2*)(QRb + rA * QPITCH + qoff);
            float2 qa1 = *(const float2*)(QRb + rA * QPITCH + qoff + 8);
            float2 qb0 = *(const float2*)(QRb + rB * QPITCH + qoff);
            float2 qb1 = *(const float2*)(QRb + rB * QPITCH + qoff + 8);
            uint32_t aAx = packhi(qa0.x, qa0.y), aAy = packhi(qa1.x, qa1.y);
            uint32_t aAz = packlo(qa0.x, qa0.y), aAw = packlo(qa1.x, qa1.y);
            uint32_t aBx = packhi(qb0.x, qb0.y), aBy = packhi(qb1.x, qb1.y);
            uint32_t aBz = packlo(qb0.x, qb0.y), aBw = packlo(qb1.x, qb1.y);
#pragma unroll
            for (int t = 0; t < 13; t++) {
                if (t < cnt) {
                    const int brow = (nt0 + t) * 8 + laneq;
                    uint4 bw = *(const uint4*)(smw + KP_OFF + brow * 80 + kc * 16 + lane4 * 4);
                    mma_bf16(c[t], aAx, aBx, aAy, aBy, bw.x, bw.y);
                    mma_bf16(c[t], aAz, aBz, aAw, aBw, bw.x, bw.y);
                    mma_bf16(c[t], aAx, aBx, aAy, aBy, bw.z, bw.w);
                }
            }
        }

        float sA = 0.f, sB = 0.f;
#pragma unroll
        for (int t = 0; t < 13; t++) {
            if (t < cnt) {
                c[t][0] = __expf(c[t][0] * 0.125f);
                c[t][1] = __expf(c[t][1] * 0.125f);
                c[t][2] = __expf(c[t][2] * 0.125f);
                c[t][3] = __expf(c[t][3] * 0.125f);
            }
        }
        if (nhalf && lane4 >= 2) {
            c[11][0] = 0.f; c[11][1] = 0.f; c[11][2] = 0.f; c[11][3] = 0.f;
        }
#pragma unroll
        for (int t = 0; t < 13; t++) {
            if (t < cnt) {
                sA += c[t][0] + c[t][1];
                sB += c[t][2] + c[t][3];
            }
        }
#pragma unroll
        for (int o = 1; o <= 2; o <<= 1) {
            sA += __shfl_xor_sync(0xffffffffu, sA, o);
            sB += __shfl_xor_sync(0xffffffffu, sB, o);
        }
        if (lane4 == 0) {
            sm[RED_OFF + rA * 2 + nhalf] = sA;
            sm[RED_OFF + rB * 2 + nhalf] = sB;
        }
        bar_pair(1 + stripe);
        sA += sm[RED_OFF + rA * 2 + (1 - nhalf)];
        sB += sm[RED_OFF + rB * 2 + (1 - nhalf)];
        const float iA = 1.0f / (12.0f * sA);
        const float iB = 1.0f / (12.0f * sB);
#pragma unroll
        for (int t = 0; t < 13; t++) {
            if (t < cnt) {
                macc[t][0] += c[t][0] * iA;
                macc[t][1] += c[t][1] * iA;
                macc[t][2] += c[t][2] * iB;
                macc[t][3] += c[t][3] * iB;
            }
        }
        __syncthreads();
    }

    uint32_t* stg = smw;
    for (int i = tid; i < QROWS * KPAD; i += K1_THREADS) stg[i] = 0u;
    __syncthreads();
#pragma unroll
    for (int t = 0; t < 13; t++) {
        if (t < cnt) {
            const int col0 = (nt0 + t) * 8 + 2 * lane4;
            const int kcg2 = col0 >> 4, rem = col0 & 15;
            const int wp = kcg2 * 16 + ((rem >> 1) & 3) * 4 + (rem >> 3);
            stg[rA * KPAD + wp]     = packhi(macc[t][0], macc[t][1]);
            stg[rA * KPAD + wp + 2] = packlo(macc[t][0], macc[t][1]);
            stg[rB * KPAD + wp]     = packhi(macc[t][2], macc[t][3]);
            stg[rB * KPAD + wp + 2] = packlo(macc[t][2], macc[t][3]);
        }
    }
    __syncthreads();
    for (int i = tid; i < QROWS * 56; i += K1_THREADS) {
        int row = i / 56, s4 = i % 56;
        int qg = q0 + row;
        if (qg < LK) {
            uint4 v = *((const uint4*)(stg + row * KPAD) + s4);
            *((uint4*)(g_attn2 + ((size_t)(hf * LK + qg) * NPAIR + p) * KPAD) + s4) = v;
        }
    }
}

// ===========================================================================
// Kernel 2: out = attn @ Wgather, bf16 2-term split, m16n8k16
// grid (6 c-tiles of 128, 196 q), 256 threads = 8 warps (2 mg x 4 ng)
// NEW: separate packed-W buffer (single), raw-W double -> 2 barriers/iter
// smem words: A 2x6144 | Wraw 2x4096 | WP 6144 | idx 224
// ===========================================================================
#define K2_THREADS 256
#define A_W 6144
#define WRAW_W 4096
#define A_OFF 0
#define WRAW_OFF (2 * A_W)               // 12288
#define WP_OFF (WRAW_OFF + 2 * WRAW_W)   // 20480
#define IDX_OFF (WP_OFF + A_W)           // 26624
#define SMEM2_BYTES ((IDX_OFF + KPAD) * 4)   // 107392

__device__ __forceinline__ void k2_load(
    int q, int c0, int tid, uint32_t smem_u32,
    const float* __restrict__ w1, const float* __restrict__ w2,
    const int* __restrict__ idxrow, int s)
{
    const int half = s / 7;
    const int kb = (s % 7) * 32;
    const int buf = s & 1;
#pragma unroll
    for (int t = 0; t < 4; t++) {
        int id = tid + t * K2_THREADS;
        int row = id >> 3, seg = id & 7;
        int nn = row >> 3, tt = row & 7;
        const void* src;
        if (half == 0) {
            src = (tt >= 1) ? (const void*)(g_attn2 +
                    ((size_t)q * NPAIR + nn * 7 + tt - 1) * KPAD + kb + seg * 4)
                            : (const void*)((const char*)g_zero4 + seg * 16);
        } else {
            src = (tt <= 6) ? (const void*)(g_attn2 +
                    ((size_t)(LK + q) * NPAIR + nn * 7 + tt) * KPAD + kb + seg * 4)
                            : (const void*)((const char*)g_zero4 + seg * 16);
        }
        cp16(smem_u32 + (uint32_t)(A_OFF + buf * A_W + row * 48 + seg * 4) * 4, src);
    }
    const float* wb = half ? w2 : w1;
#pragma unroll
    for (int t = 0; t < 4; t++) {
        int id = tid + t * K2_THREADS;
        int kr = id >> 5, seg = id & 31;
        int r = idxrow[kb + kr];
        cp16(smem_u32 + (uint32_t)(WRAW_OFF + buf * WRAW_W + kr * 128 + seg * 4) * 4,
             wb + (size_t)r * CDIM + c0 + seg * 4);
    }
    asm volatile("cp.async.commit_group;");
}

__global__ void __launch_bounds__(K2_THREADS, 2) out_tc_kernel(
    const float* __restrict__ w1, const float* __restrict__ w2,
    const int* __restrict__ idx, float* __restrict__ out)
{
    extern __shared__ uint32_t smw2[];
    int* idxrow = (int*)(smw2 + IDX_OFF);
    const int q = blockIdx.y;
    const int c0 = blockIdx.x * 128;
    const int tid = threadIdx.x;
    const int lane = tid & 31;
    const int wid = tid >> 5;
    const int mg = wid >> 2, ng = wid & 3;
    const int laneq = lane >> 2, lane4 = lane & 3;

    uint32_t smem_u32;
    asm("{ .reg .u64 t; cvta.to.shared.u64 t, %1; cvt.u32.u64 %0, t; }"
        : "=r"(smem_u32) : "l"(smw2));

    // hoisted convert geometry
    const int ccv = tid & 127;          // c column
    const int kcjv = tid >> 7;          // 0..1, advances by 2
    float acc[4][4][4];
#pragma unroll
    for (int a = 0; a < 4; a++)
#pragma unroll
        for (int b = 0; b < 4; b++)
#pragma unroll
            for (int d = 0; d < 4; d++) acc[a][b][d] = 0.f;

    for (int i = tid; i < KPAD; i += K2_THREADS)
        idxrow[i] = (i < LK) ? idx[q * LK + i] : 0;
    __syncthreads();

    k2_load(q, c0, tid, smem_u32, w1, w2, idxrow, 0);

    for (int s = 0; s < 14; s++) {
        const int buf = s & 1;
        asm volatile("cp.async.wait_group 0;");    // own group s done
        __syncthreads();                           // all cp(s) visible; MMA(s-1) done
        if (s + 1 < 14) k2_load(q, c0, tid, smem_u32, w1, w2, idxrow, s + 1);

        // ---- W convert: raw(buf) [k32][c128] f32 -> WP packed [c][48] words ----
        {
            const float* wr = (const float*)(smw2 + WRAW_OFF + buf * WRAW_W);
#pragma unroll
            for (int t = 0; t < 4; t++) {
                int kcj = kcjv + t * 2;
                int ckc = kcj >> 2, cj = kcj & 3;
                int k0 = ckc * 16 + 2 * cj;
                float f0 = wr[k0 * 128 + ccv];
                float f1 = wr[(k0 + 1) * 128 + ccv];
                float f2 = wr[(k0 + 8) * 128 + ccv];
                float f3 = wr[(k0 + 9) * 128 + ccv];
                uint4 v;
                v.x = packhi(f0, f1);
                v.y = packhi(f2, f3);
                v.z = packlo(f0, f1);
                v.w = packlo(f2, f3);
                *(uint4*)(smw2 + WP_OFF + ccv * 48 + ckc * 16 + cj * 4) = v;
            }
        }
        __syncthreads();                           // WP(s) ready

        const uint32_t* Ab = smw2 + A_OFF + buf * A_W + (mg * 64 + laneq) * 48 + lane4 * 4;
        const uint32_t* Bb = smw2 + WP_OFF + (ng * 32 + laneq) * 48 + lane4 * 4;
#pragma unroll
        for (int kc = 0; kc < 2; kc++) {
            uint4 bw[4];
#pragma unroll
            for (int nt = 0; nt < 4; nt++)
                bw[nt] = *(const uint4*)(Bb + nt * 8 * 48 + kc * 16);
#pragma unroll
            for (int mt = 0; mt < 4; mt++) {
                uint4 a0 = *(const uint4*)(Ab + mt * 16 * 48 + kc * 16);
                uint4 a1 = *(const uint4*)(Ab + (mt * 16 + 8) * 48 + kc * 16);
#pragma unroll
                for (int nt = 0; nt < 4; nt++) {
                    mma_bf16(acc[mt][nt], a0.x, a1.x, a0.y, a1.y, bw[nt].x, bw[nt].y);
                    mma_bf16(acc[mt][nt], a0.z, a1.z, a0.w, a1.w, bw[nt].x, bw[nt].y);
                    mma_bf16(acc[mt][nt], a0.x, a1.x, a0.y, a1.y, bw[nt].z, bw[nt].w);
                }
            }
        }
    }

#pragma unroll
    for (int mt = 0; mt < 4; mt++) {
#pragma unroll
        for (int nt = 0; nt < 4; nt++) {
            int mrow = mg * 64 + mt * 16 + laneq;
            int col = c0 + ng * 32 + nt * 8 + 2 * lane4;
            float* ob0 = out + ((size_t)mrow * LL + q + 1) * CDIM + col;
            float* ob1 = out + ((size_t)(mrow + 8) * LL + q + 1) * CDIM + col;
            *(float2*)ob0 = make_float2(acc[mt][nt][0], acc[mt][nt][1]);
            *(float2*)ob1 = make_float2(acc[mt][nt][2], acc[mt][nt][3]);
        }
    }
}

__global__ void zero_l0_kernel(float* __restrict__ out) {
    int i = blockIdx.x * blockDim.x + threadIdx.x;   // 128*768
    int nt = i / CDIM, cc = i - nt * CDIM;
    out[(size_t)nt * LL * CDIM + cc] = 0.f;
}

extern "C" void kernel_launch(void* const* d_in, const int* in_sizes, int n_in,
                              void* d_out, int out_size)
{
    const float* q  = (const float*)d_in[0];
    const float* k  = (const float*)d_in[1];
    const float* w1 = (const float*)d_in[2];
    const float* w2 = (const float*)d_in[3];
    const int*  idx = (const int*)d_in[4];
    float* out = (float*)d_out;

    cudaFuncSetAttribute(attn_tc_kernel, cudaFuncAttributeMaxDynamicSharedMemorySize, SMEM1_BYTES);
    cudaFuncSetAttribute(out_tc_kernel, cudaFuncAttributeMaxDynamicSharedMemorySize, SMEM2_BYTES);

    attn_tc_kernel<<<dim3(2, NPAIR, 2), K1_THREADS, SMEM1_BYTES>>>(q, k);
    zero_l0_kernel<<<96, 1024>>>(out);
    out_tc_kernel<<<dim3(6, LK), K2_THREADS, SMEM2_BYTES>>>(w1, w2, idx, out);
}